// round 13
// baseline (speedup 1.0000x reference)
#include <cuda_runtime.h>
#include <cuda_fp16.h>
#include <cstdint>
#include <math.h>

// Problem dims (fixed by the reference)
#define BB 64
#define SS 2048
#define HH 512
#define TOK (BB * SS)   // 131072
#define NEGV -1e9f

// Scratch (allocations are banned; use device globals)
__device__ float g_scores2[2 * TOK];     // partial scores (N-split halves)
__device__ float g_attn_fallback[TOK];
__device__ float g_part[8 * BB * HH];
__device__ int   g_mask_is_i32;
__device__ __half g_wh[HH * HH];
__device__ __half g_wl[HH * HH];

// ===========================================================================
// Helpers
// ===========================================================================
__device__ __forceinline__ uint32_t smem_u32(const void* p) {
    uint32_t a;
    asm("{ .reg .u64 t; cvta.to.shared.u64 t, %1; cvt.u32.u64 %0, t; }"
        : "=r"(a) : "l"(p));
    return a;
}
__device__ __forceinline__ void ldsm4(uint32_t (&r)[4], uint32_t addr) {
    asm volatile("ldmatrix.sync.aligned.m8n8.x4.shared.b16 {%0,%1,%2,%3}, [%4];"
        : "=r"(r[0]), "=r"(r[1]), "=r"(r[2]), "=r"(r[3]) : "r"(addr));
}
// fp16 in, fp32 accum
__device__ __forceinline__ void mma_f32(float (&c)[4], const uint32_t (&a)[4],
                                        uint32_t b0, uint32_t b1) {
    asm volatile("mma.sync.aligned.m16n8k16.row.col.f32.f16.f16.f32 "
        "{%0,%1,%2,%3}, {%4,%5,%6,%7}, {%8,%9}, {%0,%1,%2,%3};"
        : "+f"(c[0]), "+f"(c[1]), "+f"(c[2]), "+f"(c[3])
        : "r"(a[0]), "r"(a[1]), "r"(a[2]), "r"(a[3]), "r"(b0), "r"(b1));
}
// fp16 in, fp16 accum
__device__ __forceinline__ void mma_f16(uint32_t (&c)[2], const uint32_t (&a)[4],
                                        uint32_t b0, uint32_t b1) {
    asm volatile("mma.sync.aligned.m16n8k16.row.col.f16.f16.f16.f16 "
        "{%0,%1}, {%2,%3,%4,%5}, {%6,%7}, {%0,%1};"
        : "+r"(c[0]), "+r"(c[1])
        : "r"(a[0]), "r"(a[1]), "r"(a[2]), "r"(a[3]), "r"(b0), "r"(b1));
}
__device__ __forceinline__ void cp16(uint32_t dst, const void* src) {
    asm volatile("cp.async.cg.shared.global [%0], [%1], 16;"
        :: "r"(dst), "l"(src));
}
#define CP_COMMIT() asm volatile("cp.async.commit_group;" ::: "memory")
#define CP_WAIT1()  asm volatile("cp.async.wait_group 1;" ::: "memory")

__device__ __forceinline__ float fast_tanh(float x) {
    x = fminf(15.f, fmaxf(-15.f, x));
    float e = __expf(2.f * x);
    return __fdividef(e - 1.f, e + 1.f);
}

// ===========================================================================
// W pre-split: W fp32 -> Wh, Wl fp16 (global, done once per launch)
// ===========================================================================
__global__ __launch_bounds__(256)
void wsplit_kernel(const float* __restrict__ W,
                   __half* __restrict__ wh,
                   __half* __restrict__ wl)
{
    int idx = blockIdx.x * 256 + threadIdx.x;
#pragma unroll
    for (int j = 0; j < 4; j++) {
        int i = idx * 4 + j;
        float x = W[i];
        __half h = __float2half_rn(x);
        wh[i] = h;
        wl[i] = __float2half_rn(x - __half2float(h));
    }
}

// Tiny no-op so scores_tc lands at ncu's captured launch index (3).
__global__ void dummy_kernel() {}

// ===========================================================================
// Scores kernel: 3-term fp16 split GEMM + fused v.tanh(.+b) epilogue.
// m48n32 warp tiles (142 B/MMA), block M=96 x N=128, BK=32, 256 thr,
// 2 CTAs/SM. N-SPLIT grid (1366 x 2): each CTA does 2 of 4 nc and writes a
// partial score; softmax sums the two halves. Waves 9.2 -> tail ~2.5%.
// B: 3-stage cp.async ring, prefetch distance 2, wait_group 1 (the awaited
// group was issued 2 kt ago -> ~zero wait). Dummy commit groups keep the
// outstanding count uniform at the tail. A: LDG fp32 -> hi/lo 2-stage ring.
// ===========================================================================
#define ASTR 80                  // 32 fp16 = 64B + 16 pad
#define A_PLANE (96 * ASTR)      // 7680
#define A_STAGE (2 * A_PLANE)    // 15360 (hi+lo)
#define B_PLANE (128 * ASTR)     // 10240
#define B_STAGE (2 * B_PLANE)    // 20480 (hi+lo)
#define OFF_V    0
#define OFF_BI   2048
#define OFF_A    4096
#define OFF_B    (OFF_A + 2 * A_STAGE)      // 34816
#define SMEM_TOTAL (OFF_B + 3 * B_STAGE)    // 96256 -> 2 CTAs/SM
#define OFF_RED  OFF_B                      // reuse dead B ring for reduction

#define NTHR 256
#define BM 96
#define GRID_M ((TOK + BM - 1) / BM)        // 1366
#define NITER 32                            // 2 nc x 16 kt per CTA

__device__ __forceinline__ void issue_b(const __half* __restrict__ wh,
                                        const __half* __restrict__ wl,
                                        uint32_t dst_hi, int nc, int kt, int tid)
{
#pragma unroll
    for (int j = 0; j < 2; j++) {
        int idx = tid + j * NTHR;         // 0..511
        int row = idx >> 2;               // n row 0..127
        int c16 = idx & 3;                // 16B chunk (4 per 64B row)
        uint32_t d = dst_hi + row * ASTR + c16 * 16;
        size_t g = (size_t)(nc * 128 + row) * HH + kt * 32 + c16 * 8;
        cp16(d, wh + g);
        cp16(d + B_PLANE, wl + g);
    }
    CP_COMMIT();
}

// Convert 3 float4 (96x32 A chunk slice per thread) and store hi/lo.
__device__ __forceinline__ void store_a(const float4 (&ar)[3],
                                        char* ah, char* al, int tid)
{
#pragma unroll
    for (int j = 0; j < 3; j++) {
        int idx = tid + j * NTHR;         // 0..767
        int r  = idx >> 3;                // row 0..95
        int c  = (idx & 7) * 4;           // col (fp32 units, 0..28)
        float4 f = ar[j];
        __half h0 = __float2half_rn(f.x);
        __half h1 = __float2half_rn(f.y);
        __half h2 = __float2half_rn(f.z);
        __half h3 = __float2half_rn(f.w);
        uint32_t hh0 = ((uint32_t)__half_as_ushort(h1) << 16) | __half_as_ushort(h0);
        uint32_t hh1 = ((uint32_t)__half_as_ushort(h3) << 16) | __half_as_ushort(h2);
        __half l0 = __float2half_rn(f.x - __half2float(h0));
        __half l1 = __float2half_rn(f.y - __half2float(h1));
        __half l2 = __float2half_rn(f.z - __half2float(h2));
        __half l3 = __float2half_rn(f.w - __half2float(h3));
        uint32_t ll0 = ((uint32_t)__half_as_ushort(l1) << 16) | __half_as_ushort(l0);
        uint32_t ll1 = ((uint32_t)__half_as_ushort(l3) << 16) | __half_as_ushort(l2);
        int off = r * ASTR + c * 2;
        *(uint2*)(ah + off) = make_uint2(hh0, hh1);
        *(uint2*)(al + off) = make_uint2(ll0, ll1);
    }
}

__device__ __forceinline__ void load_a_chunk(const float* __restrict__ X,
                                             float4 (&ar)[3], int row0, int kt, int tid)
{
#pragma unroll
    for (int j = 0; j < 3; j++) {
        int idx = tid + j * NTHR;
        int r  = idx >> 3;
        int c  = (idx & 7) * 4;
        int rg = row0 + r;
        rg = rg < TOK ? rg : TOK - 1;    // tail clamp
        ar[j] = *(const float4*)(X + (size_t)rg * HH + kt * 32 + c);
    }
}

__global__ __launch_bounds__(NTHR, 2)
void scores_tc_kernel(const float* __restrict__ X,
                      const __half* __restrict__ wh,
                      const __half* __restrict__ wl,
                      const float* __restrict__ bias,
                      const float* __restrict__ v,
                      float* __restrict__ scores2)
{
    extern __shared__ char smem[];
    const int tid  = threadIdx.x;
    const int lane = tid & 31;
    const int wid  = tid >> 5;
    const int warp_m = wid & 1;        // 0..1 -> 48-row slab
    const int warp_n = wid >> 1;       // 0..3 -> 32-col slab
    const int row0 = blockIdx.x * BM;
    const int ncg  = blockIdx.y;       // 0 -> nc {0,1}, 1 -> nc {2,3}

    const uint32_t sb = smem_u32(smem);
    float* sv  = (float*)(smem + OFF_V);
    float* sbi = (float*)(smem + OFF_BI);
    for (int i = tid; i < HH; i += NTHR) { sv[i] = v[i]; sbi[i] = bias[i]; }

    // Prologue: B groups for it=0 and it=1 (3-stage ring, distance 2).
    issue_b(wh, wl, sb + OFF_B, 2 * ncg, 0, tid);
    issue_b(wh, wl, sb + OFF_B + B_STAGE, 2 * ncg, 1, tid);

    // Prologue: A chunk kt=0 -> stage 0.
    {
        float4 ar[3];
        load_a_chunk(X, ar, row0, 0, tid);
        store_a(ar, smem + OFF_A, smem + OFF_A + A_PLANE, tid);
    }

    // ldmatrix lane offsets (bytes)
    const int a_off = (warp_m * 48 + (lane & 15)) * ASTR + ((lane >> 4) << 4);
    const int b_off = (warp_n * 32 + (lane & 7) + ((lane >> 4) << 3)) * ASTR
                    + (((lane >> 3) & 1) << 4);

    float sacc[6] = {0.f, 0.f, 0.f, 0.f, 0.f, 0.f};   // [mi*2 + half]

    for (int ncl = 0; ncl < 2; ncl++) {
        const int nc = 2 * ncg + ncl;
        float acc[3][4][4];
        uint32_t corr[3][4][2];
#pragma unroll
        for (int mi = 0; mi < 3; mi++)
#pragma unroll
            for (int ni = 0; ni < 4; ni++) {
#pragma unroll
                for (int c = 0; c < 4; c++) acc[mi][ni][c] = 0.f;
                corr[mi][ni][0] = 0u; corr[mi][ni][1] = 0u;
            }

        for (int kt = 0; kt < 16; kt++) {
            const int it = ncl * 16 + kt;
            const int abuf = it & 1;
            const int bbuf = it % 3;

            CP_WAIT1();             // group(it) complete (issued 2 kt ago)
            __syncthreads();        // visibility of A store + others' B copies

            {   // Issue B for it+2 (or dummy commit to keep count uniform).
                int nit = it + 2;
                if (nit < NITER) {
                    issue_b(wh, wl, sb + OFF_B + (nit % 3) * B_STAGE,
                            2 * ncg + (nit >> 4), nit & 15, tid);
                } else {
                    CP_COMMIT();
                }
            }

            // Prefetch next A chunk (fp32) into regs; latency hidden by MMAs.
            float4 ar[3];
            const bool have_next_a = (it < NITER - 1);
            if (have_next_a) load_a_chunk(X, ar, row0, (kt + 1) & 15, tid);

            const uint32_t ah_base = sb + OFF_A + abuf * A_STAGE + a_off;
            const uint32_t al_base = ah_base + A_PLANE;
            const uint32_t bh_b = sb + OFF_B + bbuf * B_STAGE + b_off;
            const uint32_t bl_b = bh_b + B_PLANE;

#pragma unroll
            for (int k16 = 0; k16 < 2; k16++) {
                const int ko = k16 * 32;
                uint32_t ah0[4], ah1[4], ah2[4], al0[4], al1[4], al2[4];
                ldsm4(ah0, ah_base + ko);
                ldsm4(ah1, ah_base + 1280 + ko);    // +16 rows
                ldsm4(ah2, ah_base + 2560 + ko);    // +32 rows
                ldsm4(al0, al_base + ko);
                ldsm4(al1, al_base + 1280 + ko);
                ldsm4(al2, al_base + 2560 + ko);
#pragma unroll
                for (int np = 0; np < 2; np++) {
                    const int bo = np * 1280 + ko;
                    uint32_t bh[4], bl[4];
                    ldsm4(bh, bh_b + bo);
                    ldsm4(bl, bl_b + bo);
                    // main terms: fp32 accumulate
                    mma_f32(acc[0][2 * np],     ah0, bh[0], bh[1]);
                    mma_f32(acc[0][2 * np + 1], ah0, bh[2], bh[3]);
                    mma_f32(acc[1][2 * np],     ah1, bh[0], bh[1]);
                    mma_f32(acc[1][2 * np + 1], ah1, bh[2], bh[3]);
                    mma_f32(acc[2][2 * np],     ah2, bh[0], bh[1]);
                    mma_f32(acc[2][2 * np + 1], ah2, bh[2], bh[3]);
                    // corrections: fp16 accumulate; RAW pairs spaced.
                    mma_f16(corr[0][2 * np],     ah0, bl[0], bl[1]);
                    mma_f16(corr[0][2 * np + 1], ah0, bl[2], bl[3]);
                    mma_f16(corr[1][2 * np],     ah1, bl[0], bl[1]);
                    mma_f16(corr[1][2 * np + 1], ah1, bl[2], bl[3]);
                    mma_f16(corr[2][2 * np],     ah2, bl[0], bl[1]);
                    mma_f16(corr[2][2 * np + 1], ah2, bl[2], bl[3]);
                    mma_f16(corr[0][2 * np],     al0, bh[0], bh[1]);
                    mma_f16(corr[0][2 * np + 1], al0, bh[2], bh[3]);
                    mma_f16(corr[1][2 * np],     al1, bh[0], bh[1]);
                    mma_f16(corr[1][2 * np + 1], al1, bh[2], bh[3]);
                    mma_f16(corr[2][2 * np],     al2, bh[0], bh[1]);
                    mma_f16(corr[2][2 * np + 1], al2, bh[2], bh[3]);
                }
            }

            // Convert + store next A chunk into the other stage.
            if (have_next_a) {
                char* ahd = smem + OFF_A + (abuf ^ 1) * A_STAGE;
                store_a(ar, ahd, ahd + A_PLANE, tid);
            }
        }

        // fused partial epilogue for this 128-col chunk
#pragma unroll
        for (int mi = 0; mi < 3; mi++)
#pragma unroll
            for (int ni = 0; ni < 4; ni++) {
                float2 c01 = __half22float2(*(const __half2*)&corr[mi][ni][0]);
                float2 c23 = __half22float2(*(const __half2*)&corr[mi][ni][1]);
                float cf[4] = {c01.x, c01.y, c23.x, c23.y};
#pragma unroll
                for (int c = 0; c < 4; c++) {
                    int n = nc * 128 + warp_n * 32 + ni * 8 + (lane & 3) * 2 + (c & 1);
                    float t = fast_tanh(acc[mi][ni][c] + cf[c] + sbi[n]);
                    sacc[mi * 2 + (c >> 1)] = fmaf(sv[n], t, sacc[mi * 2 + (c >> 1)]);
                }
            }
    }

    // cross-warp reduction: red[96][16] aliases the (dead) B ring.
    float* red = (float*)(smem + OFF_RED);
    __syncthreads();   // all B/A reads done before aliasing
#pragma unroll
    for (int mi = 0; mi < 3; mi++)
#pragma unroll
        for (int half = 0; half < 2; half++) {
            int m = warp_m * 48 + mi * 16 + half * 8 + (lane >> 2);
            red[m * 16 + warp_n * 4 + (lane & 3)] = sacc[mi * 2 + half];
        }
    __syncthreads();
    if (tid < BM) {
        float s = 0.f;
#pragma unroll
        for (int j = 0; j < 16; j++) s += red[tid * 16 + j];
        if (row0 + tid < TOK) scores2[ncg * TOK + row0 + tid] = s;
    }
}

// ---------------------------------------------------------------------------
// Mask dtype detection: numpy bool may be serialized as int32 or uint8.
// ---------------------------------------------------------------------------
__global__ void detect_mask_kernel(const unsigned* __restrict__ mask_words)
{
    if (threadIdx.x == 0) {
        int ok = 1;
        for (int i = 0; i < 256; i++) {
            if (mask_words[i] > 1u) { ok = 0; break; }
        }
        g_mask_is_i32 = ok;
    }
}

// ---------------------------------------------------------------------------
// Masked softmax over S per batch row (sums the two N-split score halves).
// ---------------------------------------------------------------------------
__global__ __launch_bounds__(256)
void softmax_kernel(const float* __restrict__ scores2,
                    const void* __restrict__ mask,
                    float* __restrict__ attn)
{
    const int b = blockIdx.x;
    const int tid = threadIdx.x;
    __shared__ float sred[256];
    __shared__ int s_is_i32;

    if (tid == 0) s_is_i32 = g_mask_is_i32;
    __syncthreads();
    const int is_i32 = s_is_i32;

    const int* mi = (const int*)mask;
    const unsigned char* mu = (const unsigned char*)mask;

    float vals[8];
    float mx = -INFINITY;
#pragma unroll
    for (int j = 0; j < 8; j++) {
        int idx = b * SS + tid + j * 256;
        float sc = scores2[idx] + scores2[TOK + idx];
        bool m = is_i32 ? (mi[idx] != 0) : (mu[idx] != 0);
        sc = m ? sc : NEGV;
        vals[j] = sc;
        mx = fmaxf(mx, sc);
    }
    sred[tid] = mx; __syncthreads();
    for (int off = 128; off > 0; off >>= 1) {
        if (tid < off) sred[tid] = fmaxf(sred[tid], sred[tid + off]);
        __syncthreads();
    }
    mx = sred[0]; __syncthreads();

    float sum = 0.f;
#pragma unroll
    for (int j = 0; j < 8; j++) {
        vals[j] = expf(vals[j] - mx);
        sum += vals[j];
    }
    sred[tid] = sum; __syncthreads();
    for (int off = 128; off > 0; off >>= 1) {
        if (tid < off) sred[tid] += sred[tid + off];
        __syncthreads();
    }
    sum = sred[0];

    float inv = 1.f / sum;
#pragma unroll
    for (int j = 0; j < 8; j++) {
        attn[b * SS + tid + j * 256] = vals[j] * inv;
    }
}

// ---------------------------------------------------------------------------
// weighted_output[b,h] = sum_s attn[b,s] * X[b,s,h]
// Stage 1: S split 8 ways -> partials (grid 64x4x8). Stage 2: reduce.
// ---------------------------------------------------------------------------
__global__ __launch_bounds__(128)
void weighted_part_kernel(const float* __restrict__ X,
                          const float* __restrict__ attn,
                          float* __restrict__ part)
{
    const int b  = blockIdx.x;
    const int h  = blockIdx.y * 128 + threadIdx.x;
    const int sc = blockIdx.z;              // 0..7, 256 s each
    const int s0 = sc * 256;
    const float* xb = X + (size_t)b * SS * HH + (size_t)s0 * HH + h;
    const float* ab = attn + b * SS + s0;

    float a0 = 0.f, a1 = 0.f, a2 = 0.f, a3 = 0.f;
#pragma unroll 4
    for (int s = 0; s < 256; s += 4) {
        a0 = fmaf(__ldg(&ab[s + 0]), __ldg(&xb[(size_t)(s + 0) * HH]), a0);
        a1 = fmaf(__ldg(&ab[s + 1]), __ldg(&xb[(size_t)(s + 1) * HH]), a1);
        a2 = fmaf(__ldg(&ab[s + 2]), __ldg(&xb[(size_t)(s + 2) * HH]), a2);
        a3 = fmaf(__ldg(&ab[s + 3]), __ldg(&xb[(size_t)(s + 3) * HH]), a3);
    }
    part[((size_t)sc * BB + b) * HH + h] = (a0 + a1) + (a2 + a3);
}

__global__ __launch_bounds__(256)
void weighted_reduce_kernel(const float* __restrict__ part,
                            float* __restrict__ out)
{
    int idx = blockIdx.x * 256 + threadIdx.x;   // BB*HH = 32768
    float s = 0.f;
#pragma unroll
    for (int j = 0; j < 8; j++) s += part[j * BB * HH + idx];
    out[idx] = s;
}

// ---------------------------------------------------------------------------
extern "C" void kernel_launch(void* const* d_in, const int* in_sizes, int n_in,
                              void* d_out, int out_size)
{
    const float* X    = (const float*)d_in[0];   // [B,S,H]
    const void*  mask = d_in[1];                 // [B,S] bool (int32 or uint8)
    const float* W    = (const float*)d_in[2];   // [H,H]
    const float* bias = (const float*)d_in[3];   // [H]
    const float* v    = (const float*)d_in[4];   // [H]
    float* out = (float*)d_out;

    // Output layout: weighted_output [B,H] first, attn_weights [B,S] second.
    float* attn;
    if (out_size >= BB * HH + TOK) {
        attn = out + BB * HH;
    } else {
        void* p = nullptr;
        cudaGetSymbolAddress(&p, g_attn_fallback);
        attn = (float*)p;
    }
    void* sp = nullptr; cudaGetSymbolAddress(&sp, g_scores2);
    float* scores2 = (float*)sp;
    void* pp = nullptr; cudaGetSymbolAddress(&pp, g_part);
    float* part = (float*)pp;
    void* whp = nullptr; cudaGetSymbolAddress(&whp, g_wh);
    void* wlp = nullptr; cudaGetSymbolAddress(&wlp, g_wl);
    __half* wh = (__half*)whp;
    __half* wl = (__half*)wlp;

    cudaFuncSetAttribute(scores_tc_kernel,
                         cudaFuncAttributeMaxDynamicSharedMemorySize, SMEM_TOTAL);

    detect_mask_kernel<<<1, 32>>>((const unsigned*)mask);   // idx 0
    wsplit_kernel<<<HH * HH / 1024, 256>>>(W, wh, wl);      // idx 1
    dummy_kernel<<<1, 32>>>();                              // idx 2 (ncu slot shim)
    scores_tc_kernel<<<dim3(GRID_M, 2), NTHR, SMEM_TOTAL>>>(X, wh, wl, bias, v, scores2); // idx 3
    softmax_kernel<<<BB, 256>>>(scores2, mask, attn);
    weighted_part_kernel<<<dim3(BB, HH / 128, 8), 128>>>(X, attn, part);
    weighted_reduce_kernel<<<BB * HH / 256, 256>>>(part, out);
}

// round 14
// speedup vs baseline: 1.0216x; 1.0216x over previous
#include <cuda_runtime.h>
#include <cuda_fp16.h>
#include <cstdint>
#include <math.h>

// Problem dims (fixed by the reference)
#define BB 64
#define SS 2048
#define HH 512
#define TOK (BB * SS)   // 131072
#define NEGV -1e9f

// Scratch (allocations are banned; use device globals)
__device__ float g_scores[TOK];
__device__ float g_attn_fallback[TOK];
__device__ float g_part[16 * BB * HH];
__device__ int   g_mask_is_i32;
__device__ __half g_wh[HH * HH];
__device__ __half g_wl[HH * HH];

// ===========================================================================
// Helpers
// ===========================================================================
__device__ __forceinline__ uint32_t smem_u32(const void* p) {
    uint32_t a;
    asm("{ .reg .u64 t; cvta.to.shared.u64 t, %1; cvt.u32.u64 %0, t; }"
        : "=r"(a) : "l"(p));
    return a;
}
__device__ __forceinline__ void ldsm4(uint32_t (&r)[4], uint32_t addr) {
    asm volatile("ldmatrix.sync.aligned.m8n8.x4.shared.b16 {%0,%1,%2,%3}, [%4];"
        : "=r"(r[0]), "=r"(r[1]), "=r"(r[2]), "=r"(r[3]) : "r"(addr));
}
// fp16 in, fp32 accum
__device__ __forceinline__ void mma_f32(float (&c)[4], const uint32_t (&a)[4],
                                        uint32_t b0, uint32_t b1) {
    asm volatile("mma.sync.aligned.m16n8k16.row.col.f32.f16.f16.f32 "
        "{%0,%1,%2,%3}, {%4,%5,%6,%7}, {%8,%9}, {%0,%1,%2,%3};"
        : "+f"(c[0]), "+f"(c[1]), "+f"(c[2]), "+f"(c[3])
        : "r"(a[0]), "r"(a[1]), "r"(a[2]), "r"(a[3]), "r"(b0), "r"(b1));
}
// fp16 in, fp16 accum
__device__ __forceinline__ void mma_f16(uint32_t (&c)[2], const uint32_t (&a)[4],
                                        uint32_t b0, uint32_t b1) {
    asm volatile("mma.sync.aligned.m16n8k16.row.col.f16.f16.f16.f16 "
        "{%0,%1}, {%2,%3,%4,%5}, {%6,%7}, {%0,%1};"
        : "+r"(c[0]), "+r"(c[1])
        : "r"(a[0]), "r"(a[1]), "r"(a[2]), "r"(a[3]), "r"(b0), "r"(b1));
}
__device__ __forceinline__ void cp16(uint32_t dst, const void* src) {
    asm volatile("cp.async.cg.shared.global [%0], [%1], 16;"
        :: "r"(dst), "l"(src));
}
#define CP_COMMIT() asm volatile("cp.async.commit_group;" ::: "memory")
#define CP_WAIT0()  asm volatile("cp.async.wait_group 0;" ::: "memory")

__device__ __forceinline__ float fast_tanh(float x) {
    x = fminf(15.f, fmaxf(-15.f, x));
    float e = __expf(2.f * x);
    return __fdividef(e - 1.f, e + 1.f);
}

// ===========================================================================
// W pre-split: W fp32 -> Wh, Wl fp16 (global, done once per launch)
// ===========================================================================
__global__ __launch_bounds__(256)
void wsplit_kernel(const float* __restrict__ W,
                   __half* __restrict__ wh,
                   __half* __restrict__ wl)
{
    int idx = blockIdx.x * 256 + threadIdx.x;
#pragma unroll
    for (int j = 0; j < 4; j++) {
        int i = idx * 4 + j;
        float x = W[i];
        __half h = __float2half_rn(x);
        wh[i] = h;
        wl[i] = __float2half_rn(x - __half2float(h));
    }
}

// ===========================================================================
// Scores kernel (R12 config — best measured): 3-term fp16 split GEMM +
// fused v.tanh(.+b) epilogue. m48n32 warp tiles, block M=96 x N=128, BK=32,
// 256 thr, 2 CTAs/SM, A streamed (LDG fp32 -> hi/lo ring), B via cp.async.
// ===========================================================================
#define ASTR 80                  // 32 fp16 = 64B + 16 pad
#define A_PLANE (96 * ASTR)      // 7680
#define A_STAGE (2 * A_PLANE)    // 15360 (hi+lo)
#define B_PLANE (128 * ASTR)     // 10240
#define B_STAGE (2 * B_PLANE)    // 20480 (hi+lo)
#define OFF_V    0
#define OFF_BI   2048
#define OFF_A    4096
#define OFF_B    (OFF_A + 2 * A_STAGE)      // 34816
#define SMEM_TOTAL (OFF_B + 2 * B_STAGE)    // 75776 -> 2 CTAs/SM
#define OFF_RED  OFF_B                      // reuse dead B ring for reduction

#define NTHR 256
#define BM 96
#define GRID_M ((TOK + BM - 1) / BM)        // 1366

__device__ __forceinline__ void issue_b(const __half* __restrict__ wh,
                                        const __half* __restrict__ wl,
                                        uint32_t dst_hi, int nc, int kt, int tid)
{
#pragma unroll
    for (int j = 0; j < 2; j++) {
        int idx = tid + j * NTHR;         // 0..511
        int row = idx >> 2;               // n row 0..127
        int c16 = idx & 3;                // 16B chunk (4 per 64B row)
        uint32_t d = dst_hi + row * ASTR + c16 * 16;
        size_t g = (size_t)(nc * 128 + row) * HH + kt * 32 + c16 * 8;
        cp16(d, wh + g);
        cp16(d + B_PLANE, wl + g);
    }
    CP_COMMIT();
}

// Convert 3 float4 (96x32 A chunk slice per thread) and store hi/lo.
__device__ __forceinline__ void store_a(const float4 (&ar)[3],
                                        char* ah, char* al, int tid)
{
#pragma unroll
    for (int j = 0; j < 3; j++) {
        int idx = tid + j * NTHR;         // 0..767
        int r  = idx >> 3;                // row 0..95
        int c  = (idx & 7) * 4;           // col (fp32 units, 0..28)
        float4 f = ar[j];
        __half h0 = __float2half_rn(f.x);
        __half h1 = __float2half_rn(f.y);
        __half h2 = __float2half_rn(f.z);
        __half h3 = __float2half_rn(f.w);
        uint32_t hh0 = ((uint32_t)__half_as_ushort(h1) << 16) | __half_as_ushort(h0);
        uint32_t hh1 = ((uint32_t)__half_as_ushort(h3) << 16) | __half_as_ushort(h2);
        __half l0 = __float2half_rn(f.x - __half2float(h0));
        __half l1 = __float2half_rn(f.y - __half2float(h1));
        __half l2 = __float2half_rn(f.z - __half2float(h2));
        __half l3 = __float2half_rn(f.w - __half2float(h3));
        uint32_t ll0 = ((uint32_t)__half_as_ushort(l1) << 16) | __half_as_ushort(l0);
        uint32_t ll1 = ((uint32_t)__half_as_ushort(l3) << 16) | __half_as_ushort(l2);
        int off = r * ASTR + c * 2;
        *(uint2*)(ah + off) = make_uint2(hh0, hh1);
        *(uint2*)(al + off) = make_uint2(ll0, ll1);
    }
}

__device__ __forceinline__ void load_a_chunk(const float* __restrict__ X,
                                             float4 (&ar)[3], int row0, int kt, int tid)
{
#pragma unroll
    for (int j = 0; j < 3; j++) {
        int idx = tid + j * NTHR;
        int r  = idx >> 3;
        int c  = (idx & 7) * 4;
        int rg = row0 + r;
        rg = rg < TOK ? rg : TOK - 1;    // tail clamp
        ar[j] = *(const float4*)(X + (size_t)rg * HH + kt * 32 + c);
    }
}

__global__ __launch_bounds__(NTHR, 2)
void scores_tc_kernel(const float* __restrict__ X,
                      const __half* __restrict__ wh,
                      const __half* __restrict__ wl,
                      const float* __restrict__ bias,
                      const float* __restrict__ v,
                      float* __restrict__ scores)
{
    extern __shared__ char smem[];
    const int tid  = threadIdx.x;
    const int lane = tid & 31;
    const int wid  = tid >> 5;
    const int warp_m = wid & 1;        // 0..1 -> 48-row slab
    const int warp_n = wid >> 1;       // 0..3 -> 32-col slab
    const int row0 = blockIdx.x * BM;

    const uint32_t sb = smem_u32(smem);
    float* sv  = (float*)(smem + OFF_V);
    float* sbi = (float*)(smem + OFF_BI);
    for (int i = tid; i < HH; i += NTHR) { sv[i] = v[i]; sbi[i] = bias[i]; }

    // Prefetch first B tile (it = 0 -> buf 0).
    issue_b(wh, wl, sb + OFF_B, 0, 0, tid);

    // Prologue: A chunk kt=0 -> stage 0.
    {
        float4 ar[3];
        load_a_chunk(X, ar, row0, 0, tid);
        store_a(ar, smem + OFF_A, smem + OFF_A + A_PLANE, tid);
    }

    // ldmatrix lane offsets (bytes)
    const int a_off = (warp_m * 48 + (lane & 15)) * ASTR + ((lane >> 4) << 4);
    const int b_off = (warp_n * 32 + (lane & 7) + ((lane >> 4) << 3)) * ASTR
                    + (((lane >> 3) & 1) << 4);

    float sacc[6] = {0.f, 0.f, 0.f, 0.f, 0.f, 0.f};   // [mi*2 + half]

    for (int nc = 0; nc < 4; nc++) {
        float acc[3][4][4];
        uint32_t corr[3][4][2];
#pragma unroll
        for (int mi = 0; mi < 3; mi++)
#pragma unroll
            for (int ni = 0; ni < 4; ni++) {
#pragma unroll
                for (int c = 0; c < 4; c++) acc[mi][ni][c] = 0.f;
                corr[mi][ni][0] = 0u; corr[mi][ni][1] = 0u;
            }

        for (int kt = 0; kt < 16; kt++) {
            const int it = nc * 16 + kt;
            const int buf = it & 1;
            const bool have_next = (it < 63);

            CP_WAIT0();
            __syncthreads();        // A+B stage(kt) ready; prev stages free

            if (have_next) {
                int nit = it + 1;
                issue_b(wh, wl, sb + OFF_B + (buf ^ 1) * B_STAGE,
                        nit >> 4, nit & 15, tid);
            }

            // Prefetch next A chunk (fp32) into regs; latency hidden by MMAs.
            float4 ar[3];
            if (have_next) load_a_chunk(X, ar, row0, (kt + 1) & 15, tid);

            const uint32_t ah_base = sb + OFF_A + buf * A_STAGE + a_off;
            const uint32_t al_base = ah_base + A_PLANE;
            const uint32_t bh_b = sb + OFF_B + buf * B_STAGE + b_off;
            const uint32_t bl_b = bh_b + B_PLANE;

#pragma unroll
            for (int k16 = 0; k16 < 2; k16++) {
                const int ko = k16 * 32;
                uint32_t ah0[4], ah1[4], ah2[4], al0[4], al1[4], al2[4];
                ldsm4(ah0, ah_base + ko);
                ldsm4(ah1, ah_base + 1280 + ko);    // +16 rows
                ldsm4(ah2, ah_base + 2560 + ko);    // +32 rows
                ldsm4(al0, al_base + ko);
                ldsm4(al1, al_base + 1280 + ko);
                ldsm4(al2, al_base + 2560 + ko);
#pragma unroll
                for (int np = 0; np < 2; np++) {
                    const int bo = np * 1280 + ko;
                    uint32_t bh[4], bl[4];
                    ldsm4(bh, bh_b + bo);
                    ldsm4(bl, bl_b + bo);
                    // main terms: fp32 accumulate
                    mma_f32(acc[0][2 * np],     ah0, bh[0], bh[1]);
                    mma_f32(acc[0][2 * np + 1], ah0, bh[2], bh[3]);
                    mma_f32(acc[1][2 * np],     ah1, bh[0], bh[1]);
                    mma_f32(acc[1][2 * np + 1], ah1, bh[2], bh[3]);
                    mma_f32(acc[2][2 * np],     ah2, bh[0], bh[1]);
                    mma_f32(acc[2][2 * np + 1], ah2, bh[2], bh[3]);
                    // corrections: fp16 accumulate; RAW pairs spaced.
                    mma_f16(corr[0][2 * np],     ah0, bl[0], bl[1]);
                    mma_f16(corr[0][2 * np + 1], ah0, bl[2], bl[3]);
                    mma_f16(corr[1][2 * np],     ah1, bl[0], bl[1]);
                    mma_f16(corr[1][2 * np + 1], ah1, bl[2], bl[3]);
                    mma_f16(corr[2][2 * np],     ah2, bl[0], bl[1]);
                    mma_f16(corr[2][2 * np + 1], ah2, bl[2], bl[3]);
                    mma_f16(corr[0][2 * np],     al0, bh[0], bh[1]);
                    mma_f16(corr[0][2 * np + 1], al0, bh[2], bh[3]);
                    mma_f16(corr[1][2 * np],     al1, bh[0], bh[1]);
                    mma_f16(corr[1][2 * np + 1], al1, bh[2], bh[3]);
                    mma_f16(corr[2][2 * np],     al2, bh[0], bh[1]);
                    mma_f16(corr[2][2 * np + 1], al2, bh[2], bh[3]);
                }
            }

            // Convert + store next A chunk into the other stage.
            if (have_next) {
                char* ahd = smem + OFF_A + (buf ^ 1) * A_STAGE;
                store_a(ar, ahd, ahd + A_PLANE, tid);
            }
        }

        // fused partial epilogue for this 128-col chunk
#pragma unroll
        for (int mi = 0; mi < 3; mi++)
#pragma unroll
            for (int ni = 0; ni < 4; ni++) {
                float2 c01 = __half22float2(*(const __half2*)&corr[mi][ni][0]);
                float2 c23 = __half22float2(*(const __half2*)&corr[mi][ni][1]);
                float cf[4] = {c01.x, c01.y, c23.x, c23.y};
#pragma unroll
                for (int c = 0; c < 4; c++) {
                    int n = nc * 128 + warp_n * 32 + ni * 8 + (lane & 3) * 2 + (c & 1);
                    float t = fast_tanh(acc[mi][ni][c] + cf[c] + sbi[n]);
                    sacc[mi * 2 + (c >> 1)] = fmaf(sv[n], t, sacc[mi * 2 + (c >> 1)]);
                }
            }
    }

    // cross-warp reduction: red[96][16] aliases the (dead) B ring.
    float* red = (float*)(smem + OFF_RED);
    __syncthreads();   // all B/A reads done before aliasing
#pragma unroll
    for (int mi = 0; mi < 3; mi++)
#pragma unroll
        for (int half = 0; half < 2; half++) {
            int m = warp_m * 48 + mi * 16 + half * 8 + (lane >> 2);
            red[m * 16 + warp_n * 4 + (lane & 3)] = sacc[mi * 2 + half];
        }
    __syncthreads();
    if (tid < BM) {
        float s = 0.f;
#pragma unroll
        for (int j = 0; j < 16; j++) s += red[tid * 16 + j];
        if (row0 + tid < TOK) scores[row0 + tid] = s;
    }
}

// ---------------------------------------------------------------------------
// Mask dtype detection: numpy bool may be serialized as int32 or uint8.
// ---------------------------------------------------------------------------
__global__ void detect_mask_kernel(const unsigned* __restrict__ mask_words)
{
    if (threadIdx.x == 0) {
        int ok = 1;
        for (int i = 0; i < 256; i++) {
            if (mask_words[i] > 1u) { ok = 0; break; }
        }
        g_mask_is_i32 = ok;
    }
}

// ---------------------------------------------------------------------------
// Masked softmax over S per batch row.
// ---------------------------------------------------------------------------
__global__ __launch_bounds__(256)
void softmax_kernel(const float* __restrict__ scores,
                    const void* __restrict__ mask,
                    float* __restrict__ attn)
{
    const int b = blockIdx.x;
    const int tid = threadIdx.x;
    __shared__ float sred[256];
    __shared__ int s_is_i32;

    if (tid == 0) s_is_i32 = g_mask_is_i32;
    __syncthreads();
    const int is_i32 = s_is_i32;

    const int* mi = (const int*)mask;
    const unsigned char* mu = (const unsigned char*)mask;

    float vals[8];
    float mx = -INFINITY;
#pragma unroll
    for (int j = 0; j < 8; j++) {
        int idx = b * SS + tid + j * 256;
        float sc = scores[idx];
        bool m = is_i32 ? (mi[idx] != 0) : (mu[idx] != 0);
        sc = m ? sc : NEGV;
        vals[j] = sc;
        mx = fmaxf(mx, sc);
    }
    sred[tid] = mx; __syncthreads();
    for (int off = 128; off > 0; off >>= 1) {
        if (tid < off) sred[tid] = fmaxf(sred[tid], sred[tid + off]);
        __syncthreads();
    }
    mx = sred[0]; __syncthreads();

    float sum = 0.f;
#pragma unroll
    for (int j = 0; j < 8; j++) {
        vals[j] = expf(vals[j] - mx);
        sum += vals[j];
    }
    sred[tid] = sum; __syncthreads();
    for (int off = 128; off > 0; off >>= 1) {
        if (tid < off) sred[tid] += sred[tid + off];
        __syncthreads();
    }
    sum = sred[0];

    float inv = 1.f / sum;
#pragma unroll
    for (int j = 0; j < 8; j++) {
        attn[b * SS + tid + j * 256] = vals[j] * inv;
    }
}

// ---------------------------------------------------------------------------
// weighted_output[b,h] = sum_s attn[b,s] * X[b,s,h]
// Stage 1: S split 16 ways, 8 independent FMA chains (grid 64x4x16).
// Stage 2: reduce 16 partials.
// ---------------------------------------------------------------------------
__global__ __launch_bounds__(128)
void weighted_part_kernel(const float* __restrict__ X,
                          const float* __restrict__ attn,
                          float* __restrict__ part)
{
    const int b  = blockIdx.x;
    const int h  = blockIdx.y * 128 + threadIdx.x;
    const int sc = blockIdx.z;              // 0..15, 128 s each
    const int s0 = sc * 128;
    const float* xb = X + (size_t)b * SS * HH + (size_t)s0 * HH + h;
    const float* ab = attn + b * SS + s0;

    float a0 = 0.f, a1 = 0.f, a2 = 0.f, a3 = 0.f;
    float a4 = 0.f, a5 = 0.f, a6 = 0.f, a7 = 0.f;
#pragma unroll 4
    for (int s = 0; s < 128; s += 8) {
        a0 = fmaf(__ldg(&ab[s + 0]), __ldg(&xb[(size_t)(s + 0) * HH]), a0);
        a1 = fmaf(__ldg(&ab[s + 1]), __ldg(&xb[(size_t)(s + 1) * HH]), a1);
        a2 = fmaf(__ldg(&ab[s + 2]), __ldg(&xb[(size_t)(s + 2) * HH]), a2);
        a3 = fmaf(__ldg(&ab[s + 3]), __ldg(&xb[(size_t)(s + 3) * HH]), a3);
        a4 = fmaf(__ldg(&ab[s + 4]), __ldg(&xb[(size_t)(s + 4) * HH]), a4);
        a5 = fmaf(__ldg(&ab[s + 5]), __ldg(&xb[(size_t)(s + 5) * HH]), a5);
        a6 = fmaf(__ldg(&ab[s + 6]), __ldg(&xb[(size_t)(s + 6) * HH]), a6);
        a7 = fmaf(__ldg(&ab[s + 7]), __ldg(&xb[(size_t)(s + 7) * HH]), a7);
    }
    part[((size_t)sc * BB + b) * HH + h] =
        ((a0 + a1) + (a2 + a3)) + ((a4 + a5) + (a6 + a7));
}

__global__ __launch_bounds__(256)
void weighted_reduce_kernel(const float* __restrict__ part,
                            float* __restrict__ out)
{
    int idx = blockIdx.x * 256 + threadIdx.x;   // BB*HH = 32768
    float s = 0.f;
#pragma unroll
    for (int j = 0; j < 16; j++) s += part[j * BB * HH + idx];
    out[idx] = s;
}

// ---------------------------------------------------------------------------
extern "C" void kernel_launch(void* const* d_in, const int* in_sizes, int n_in,
                              void* d_out, int out_size)
{
    const float* X    = (const float*)d_in[0];   // [B,S,H]
    const void*  mask = d_in[1];                 // [B,S] bool (int32 or uint8)
    const float* W    = (const float*)d_in[2];   // [H,H]
    const float* bias = (const float*)d_in[3];   // [H]
    const float* v    = (const float*)d_in[4];   // [H]
    float* out = (float*)d_out;

    // Output layout: weighted_output [B,H] first, attn_weights [B,S] second.
    float* attn;
    if (out_size >= BB * HH + TOK) {
        attn = out + BB * HH;
    } else {
        void* p = nullptr;
        cudaGetSymbolAddress(&p, g_attn_fallback);
        attn = (float*)p;
    }
    void* sp = nullptr; cudaGetSymbolAddress(&sp, g_scores);
    float* scores = (float*)sp;
    void* pp = nullptr; cudaGetSymbolAddress(&pp, g_part);
    float* part = (float*)pp;
    void* whp = nullptr; cudaGetSymbolAddress(&whp, g_wh);
    void* wlp = nullptr; cudaGetSymbolAddress(&wlp, g_wl);
    __half* wh = (__half*)whp;
    __half* wl = (__half*)wlp;

    cudaFuncSetAttribute(scores_tc_kernel,
                         cudaFuncAttributeMaxDynamicSharedMemorySize, SMEM_TOTAL);

    detect_mask_kernel<<<1, 32>>>((const unsigned*)mask);
    wsplit_kernel<<<HH * HH / 1024, 256>>>(W, wh, wl);
    scores_tc_kernel<<<GRID_M, NTHR, SMEM_TOTAL>>>(X, wh, wl, bias, v, scores);
    softmax_kernel<<<BB, 256>>>(scores, mask, attn);
    weighted_part_kernel<<<dim3(BB, HH / 128, 16), 128>>>(X, attn, part);
    weighted_reduce_kernel<<<BB * HH / 256, 256>>>(part, out);
}

// round 15
// speedup vs baseline: 1.0410x; 1.0189x over previous
#include <cuda_runtime.h>
#include <cuda_fp16.h>
#include <cstdint>
#include <math.h>

// Problem dims (fixed by the reference)
#define BB 64
#define SS 2048
#define HH 512
#define TOK (BB * SS)   // 131072
#define NEGV -1e9f

// Scratch (allocations are banned; use device globals)
__device__ float g_scores[TOK];
__device__ float g_attn_fallback[TOK];
__device__ float g_part[16 * BB * HH];
__device__ int   g_mask_is_i32;
__device__ __half g_wh[HH * HH];
__device__ __half g_wl[HH * HH];

// ===========================================================================
// Helpers
// ===========================================================================
__device__ __forceinline__ uint32_t smem_u32(const void* p) {
    uint32_t a;
    asm("{ .reg .u64 t; cvta.to.shared.u64 t, %1; cvt.u32.u64 %0, t; }"
        : "=r"(a) : "l"(p));
    return a;
}
__device__ __forceinline__ void ldsm4(uint32_t (&r)[4], uint32_t addr) {
    asm volatile("ldmatrix.sync.aligned.m8n8.x4.shared.b16 {%0,%1,%2,%3}, [%4];"
        : "=r"(r[0]), "=r"(r[1]), "=r"(r[2]), "=r"(r[3]) : "r"(addr));
}
// fp16 in, fp32 accum
__device__ __forceinline__ void mma_f32(float (&c)[4], const uint32_t (&a)[4],
                                        uint32_t b0, uint32_t b1) {
    asm volatile("mma.sync.aligned.m16n8k16.row.col.f32.f16.f16.f32 "
        "{%0,%1,%2,%3}, {%4,%5,%6,%7}, {%8,%9}, {%0,%1,%2,%3};"
        : "+f"(c[0]), "+f"(c[1]), "+f"(c[2]), "+f"(c[3])
        : "r"(a[0]), "r"(a[1]), "r"(a[2]), "r"(a[3]), "r"(b0), "r"(b1));
}
// fp16 in, fp16 accum
__device__ __forceinline__ void mma_f16(uint32_t (&c)[2], const uint32_t (&a)[4],
                                        uint32_t b0, uint32_t b1) {
    asm volatile("mma.sync.aligned.m16n8k16.row.col.f16.f16.f16.f16 "
        "{%0,%1}, {%2,%3,%4,%5}, {%6,%7}, {%0,%1};"
        : "+r"(c[0]), "+r"(c[1])
        : "r"(a[0]), "r"(a[1]), "r"(a[2]), "r"(a[3]), "r"(b0), "r"(b1));
}
__device__ __forceinline__ void cp16(uint32_t dst, const void* src) {
    asm volatile("cp.async.cg.shared.global [%0], [%1], 16;"
        :: "r"(dst), "l"(src));
}
#define CP_COMMIT() asm volatile("cp.async.commit_group;" ::: "memory")
#define CP_WAIT0()  asm volatile("cp.async.wait_group 0;" ::: "memory")

__device__ __forceinline__ float fast_tanh(float x) {
    x = fminf(15.f, fmaxf(-15.f, x));
    float e = __expf(2.f * x);
    return __fdividef(e - 1.f, e + 1.f);
}

// ===========================================================================
// W pre-split: W fp32 -> Wh, Wl fp16 (global, done once per launch)
// ===========================================================================
__global__ __launch_bounds__(256)
void wsplit_kernel(const float* __restrict__ W,
                   __half* __restrict__ wh,
                   __half* __restrict__ wl)
{
    int idx = blockIdx.x * 256 + threadIdx.x;
#pragma unroll
    for (int j = 0; j < 4; j++) {
        int i = idx * 4 + j;
        float x = W[i];
        __half h = __float2half_rn(x);
        wh[i] = h;
        wl[i] = __float2half_rn(x - __half2float(h));
    }
}

// ===========================================================================
// Scores kernel (R12 config — best measured): 3-term fp16 split GEMM +
// fused v.tanh(.+b) epilogue. m48n32 warp tiles, block M=96 x N=128, BK=32,
// 256 thr, 2 CTAs/SM, A streamed (LDG fp32 -> hi/lo ring), B via cp.async.
// ===========================================================================
#define ASTR 80                  // 32 fp16 = 64B + 16 pad
#define A_PLANE (96 * ASTR)      // 7680
#define A_STAGE (2 * A_PLANE)    // 15360 (hi+lo)
#define B_PLANE (128 * ASTR)     // 10240
#define B_STAGE (2 * B_PLANE)    // 20480 (hi+lo)
#define OFF_V    0
#define OFF_BI   2048
#define OFF_A    4096
#define OFF_B    (OFF_A + 2 * A_STAGE)      // 34816
#define SMEM_TOTAL (OFF_B + 2 * B_STAGE)    // 75776 -> 2 CTAs/SM
#define OFF_RED  OFF_B                      // reuse dead B ring for reduction

#define NTHR 256
#define BM 96
#define GRID_M ((TOK + BM - 1) / BM)        // 1366

__device__ __forceinline__ void issue_b(const __half* __restrict__ wh,
                                        const __half* __restrict__ wl,
                                        uint32_t dst_hi, int nc, int kt, int tid)
{
#pragma unroll
    for (int j = 0; j < 2; j++) {
        int idx = tid + j * NTHR;         // 0..511
        int row = idx >> 2;               // n row 0..127
        int c16 = idx & 3;                // 16B chunk (4 per 64B row)
        uint32_t d = dst_hi + row * ASTR + c16 * 16;
        size_t g = (size_t)(nc * 128 + row) * HH + kt * 32 + c16 * 8;
        cp16(d, wh + g);
        cp16(d + B_PLANE, wl + g);
    }
    CP_COMMIT();
}

// Convert 3 float4 (96x32 A chunk slice per thread) and store hi/lo.
__device__ __forceinline__ void store_a(const float4 (&ar)[3],
                                        char* ah, char* al, int tid)
{
#pragma unroll
    for (int j = 0; j < 3; j++) {
        int idx = tid + j * NTHR;         // 0..767
        int r  = idx >> 3;                // row 0..95
        int c  = (idx & 7) * 4;           // col (fp32 units, 0..28)
        float4 f = ar[j];
        __half h0 = __float2half_rn(f.x);
        __half h1 = __float2half_rn(f.y);
        __half h2 = __float2half_rn(f.z);
        __half h3 = __float2half_rn(f.w);
        uint32_t hh0 = ((uint32_t)__half_as_ushort(h1) << 16) | __half_as_ushort(h0);
        uint32_t hh1 = ((uint32_t)__half_as_ushort(h3) << 16) | __half_as_ushort(h2);
        __half l0 = __float2half_rn(f.x - __half2float(h0));
        __half l1 = __float2half_rn(f.y - __half2float(h1));
        __half l2 = __float2half_rn(f.z - __half2float(h2));
        __half l3 = __float2half_rn(f.w - __half2float(h3));
        uint32_t ll0 = ((uint32_t)__half_as_ushort(l1) << 16) | __half_as_ushort(l0);
        uint32_t ll1 = ((uint32_t)__half_as_ushort(l3) << 16) | __half_as_ushort(l2);
        int off = r * ASTR + c * 2;
        *(uint2*)(ah + off) = make_uint2(hh0, hh1);
        *(uint2*)(al + off) = make_uint2(ll0, ll1);
    }
}

__device__ __forceinline__ void load_a_chunk(const float* __restrict__ X,
                                             float4 (&ar)[3], int row0, int kt, int tid)
{
#pragma unroll
    for (int j = 0; j < 3; j++) {
        int idx = tid + j * NTHR;
        int r  = idx >> 3;
        int c  = (idx & 7) * 4;
        int rg = row0 + r;
        rg = rg < TOK ? rg : TOK - 1;    // tail clamp
        ar[j] = *(const float4*)(X + (size_t)rg * HH + kt * 32 + c);
    }
}

__global__ __launch_bounds__(NTHR, 2)
void scores_tc_kernel(const float* __restrict__ X,
                      const __half* __restrict__ wh,
                      const __half* __restrict__ wl,
                      const float* __restrict__ bias,
                      const float* __restrict__ v,
                      float* __restrict__ scores)
{
    extern __shared__ char smem[];
    const int tid  = threadIdx.x;
    const int lane = tid & 31;
    const int wid  = tid >> 5;
    const int warp_m = wid & 1;        // 0..1 -> 48-row slab
    const int warp_n = wid >> 1;       // 0..3 -> 32-col slab
    const int row0 = blockIdx.x * BM;

    const uint32_t sb = smem_u32(smem);
    float* sv  = (float*)(smem + OFF_V);
    float* sbi = (float*)(smem + OFF_BI);
    for (int i = tid; i < HH; i += NTHR) { sv[i] = v[i]; sbi[i] = bias[i]; }

    // Prefetch first B tile (it = 0 -> buf 0).
    issue_b(wh, wl, sb + OFF_B, 0, 0, tid);

    // Prologue: A chunk kt=0 -> stage 0.
    {
        float4 ar[3];
        load_a_chunk(X, ar, row0, 0, tid);
        store_a(ar, smem + OFF_A, smem + OFF_A + A_PLANE, tid);
    }

    // ldmatrix lane offsets (bytes)
    const int a_off = (warp_m * 48 + (lane & 15)) * ASTR + ((lane >> 4) << 4);
    const int b_off = (warp_n * 32 + (lane & 7) + ((lane >> 4) << 3)) * ASTR
                    + (((lane >> 3) & 1) << 4);

    float sacc[6] = {0.f, 0.f, 0.f, 0.f, 0.f, 0.f};   // [mi*2 + half]

    for (int nc = 0; nc < 4; nc++) {
        float acc[3][4][4];
        uint32_t corr[3][4][2];
#pragma unroll
        for (int mi = 0; mi < 3; mi++)
#pragma unroll
            for (int ni = 0; ni < 4; ni++) {
#pragma unroll
                for (int c = 0; c < 4; c++) acc[mi][ni][c] = 0.f;
                corr[mi][ni][0] = 0u; corr[mi][ni][1] = 0u;
            }

        for (int kt = 0; kt < 16; kt++) {
            const int it = nc * 16 + kt;
            const int buf = it & 1;
            const bool have_next = (it < 63);

            CP_WAIT0();
            __syncthreads();        // A+B stage(kt) ready; prev stages free

            if (have_next) {
                int nit = it + 1;
                issue_b(wh, wl, sb + OFF_B + (buf ^ 1) * B_STAGE,
                        nit >> 4, nit & 15, tid);
            }

            // Prefetch next A chunk (fp32) into regs; latency hidden by MMAs.
            float4 ar[3];
            if (have_next) load_a_chunk(X, ar, row0, (kt + 1) & 15, tid);

            const uint32_t ah_base = sb + OFF_A + buf * A_STAGE + a_off;
            const uint32_t al_base = ah_base + A_PLANE;
            const uint32_t bh_b = sb + OFF_B + buf * B_STAGE + b_off;
            const uint32_t bl_b = bh_b + B_PLANE;

#pragma unroll
            for (int k16 = 0; k16 < 2; k16++) {
                const int ko = k16 * 32;
                uint32_t ah0[4], ah1[4], ah2[4], al0[4], al1[4], al2[4];
                ldsm4(ah0, ah_base + ko);
                ldsm4(ah1, ah_base + 1280 + ko);    // +16 rows
                ldsm4(ah2, ah_base + 2560 + ko);    // +32 rows
                ldsm4(al0, al_base + ko);
                ldsm4(al1, al_base + 1280 + ko);
                ldsm4(al2, al_base + 2560 + ko);
#pragma unroll
                for (int np = 0; np < 2; np++) {
                    const int bo = np * 1280 + ko;
                    uint32_t bh[4], bl[4];
                    ldsm4(bh, bh_b + bo);
                    ldsm4(bl, bl_b + bo);
                    // main terms: fp32 accumulate
                    mma_f32(acc[0][2 * np],     ah0, bh[0], bh[1]);
                    mma_f32(acc[0][2 * np + 1], ah0, bh[2], bh[3]);
                    mma_f32(acc[1][2 * np],     ah1, bh[0], bh[1]);
                    mma_f32(acc[1][2 * np + 1], ah1, bh[2], bh[3]);
                    mma_f32(acc[2][2 * np],     ah2, bh[0], bh[1]);
                    mma_f32(acc[2][2 * np + 1], ah2, bh[2], bh[3]);
                    // corrections: fp16 accumulate; RAW pairs spaced.
                    mma_f16(corr[0][2 * np],     ah0, bl[0], bl[1]);
                    mma_f16(corr[0][2 * np + 1], ah0, bl[2], bl[3]);
                    mma_f16(corr[1][2 * np],     ah1, bl[0], bl[1]);
                    mma_f16(corr[1][2 * np + 1], ah1, bl[2], bl[3]);
                    mma_f16(corr[2][2 * np],     ah2, bl[0], bl[1]);
                    mma_f16(corr[2][2 * np + 1], ah2, bl[2], bl[3]);
                    mma_f16(corr[0][2 * np],     al0, bh[0], bh[1]);
                    mma_f16(corr[0][2 * np + 1], al0, bh[2], bh[3]);
                    mma_f16(corr[1][2 * np],     al1, bh[0], bh[1]);
                    mma_f16(corr[1][2 * np + 1], al1, bh[2], bh[3]);
                    mma_f16(corr[2][2 * np],     al2, bh[0], bh[1]);
                    mma_f16(corr[2][2 * np + 1], al2, bh[2], bh[3]);
                }
            }

            // Convert + store next A chunk into the other stage.
            if (have_next) {
                char* ahd = smem + OFF_A + (buf ^ 1) * A_STAGE;
                store_a(ar, ahd, ahd + A_PLANE, tid);
            }
        }

        // fused partial epilogue for this 128-col chunk
#pragma unroll
        for (int mi = 0; mi < 3; mi++)
#pragma unroll
            for (int ni = 0; ni < 4; ni++) {
                float2 c01 = __half22float2(*(const __half2*)&corr[mi][ni][0]);
                float2 c23 = __half22float2(*(const __half2*)&corr[mi][ni][1]);
                float cf[4] = {c01.x, c01.y, c23.x, c23.y};
#pragma unroll
                for (int c = 0; c < 4; c++) {
                    int n = nc * 128 + warp_n * 32 + ni * 8 + (lane & 3) * 2 + (c & 1);
                    float t = fast_tanh(acc[mi][ni][c] + cf[c] + sbi[n]);
                    sacc[mi * 2 + (c >> 1)] = fmaf(sv[n], t, sacc[mi * 2 + (c >> 1)]);
                }
            }
    }

    // cross-warp reduction: red[96][16] aliases the (dead) B ring.
    float* red = (float*)(smem + OFF_RED);
    __syncthreads();   // all B/A reads done before aliasing
#pragma unroll
    for (int mi = 0; mi < 3; mi++)
#pragma unroll
        for (int half = 0; half < 2; half++) {
            int m = warp_m * 48 + mi * 16 + half * 8 + (lane >> 2);
            red[m * 16 + warp_n * 4 + (lane & 3)] = sacc[mi * 2 + half];
        }
    __syncthreads();
    if (tid < BM) {
        float s = 0.f;
#pragma unroll
        for (int j = 0; j < 16; j++) s += red[tid * 16 + j];
        if (row0 + tid < TOK) scores[row0 + tid] = s;
    }
}

// ---------------------------------------------------------------------------
// Mask dtype detection (parallel): 256 threads each test one uint32 word;
// if all words <= 1 the mask is int32-serialized bool, else uint8.
// ---------------------------------------------------------------------------
__global__ __launch_bounds__(256)
void detect_mask_kernel(const unsigned* __restrict__ mask_words)
{
    __shared__ int bad;
    if (threadIdx.x == 0) bad = 0;
    __syncthreads();
    if (mask_words[threadIdx.x] > 1u) bad = 1;
    __syncthreads();
    if (threadIdx.x == 0) g_mask_is_i32 = bad ? 0 : 1;
}

// ---------------------------------------------------------------------------
// Masked softmax over S per batch row.
// ---------------------------------------------------------------------------
__global__ __launch_bounds__(256)
void softmax_kernel(const float* __restrict__ scores,
                    const void* __restrict__ mask,
                    float* __restrict__ attn)
{
    const int b = blockIdx.x;
    const int tid = threadIdx.x;
    __shared__ float sred[256];
    __shared__ int s_is_i32;

    if (tid == 0) s_is_i32 = g_mask_is_i32;
    __syncthreads();
    const int is_i32 = s_is_i32;

    const int* mi = (const int*)mask;
    const unsigned char* mu = (const unsigned char*)mask;

    float vals[8];
    float mx = -INFINITY;
#pragma unroll
    for (int j = 0; j < 8; j++) {
        int idx = b * SS + tid + j * 256;
        float sc = scores[idx];
        bool m = is_i32 ? (mi[idx] != 0) : (mu[idx] != 0);
        sc = m ? sc : NEGV;
        vals[j] = sc;
        mx = fmaxf(mx, sc);
    }
    sred[tid] = mx; __syncthreads();
    for (int off = 128; off > 0; off >>= 1) {
        if (tid < off) sred[tid] = fmaxf(sred[tid], sred[tid + off]);
        __syncthreads();
    }
    mx = sred[0]; __syncthreads();

    float sum = 0.f;
#pragma unroll
    for (int j = 0; j < 8; j++) {
        vals[j] = expf(vals[j] - mx);
        sum += vals[j];
    }
    sred[tid] = sum; __syncthreads();
    for (int off = 128; off > 0; off >>= 1) {
        if (tid < off) sred[tid] += sred[tid + off];
        __syncthreads();
    }
    sum = sred[0];

    float inv = 1.f / sum;
#pragma unroll
    for (int j = 0; j < 8; j++) {
        attn[b * SS + tid + j * 256] = vals[j] * inv;
    }
}

// ---------------------------------------------------------------------------
// weighted_output[b,h] = sum_s attn[b,s] * X[b,s,h]
// Stage 1: S split 16 ways, 8 independent FMA chains (grid 64x4x16).
// Stage 2: reduce 16 partials.
// ---------------------------------------------------------------------------
__global__ __launch_bounds__(128)
void weighted_part_kernel(const float* __restrict__ X,
                          const float* __restrict__ attn,
                          float* __restrict__ part)
{
    const int b  = blockIdx.x;
    const int h  = blockIdx.y * 128 + threadIdx.x;
    const int sc = blockIdx.z;              // 0..15, 128 s each
    const int s0 = sc * 128;
    const float* xb = X + (size_t)b * SS * HH + (size_t)s0 * HH + h;
    const float* ab = attn + b * SS + s0;

    float a0 = 0.f, a1 = 0.f, a2 = 0.f, a3 = 0.f;
    float a4 = 0.f, a5 = 0.f, a6 = 0.f, a7 = 0.f;
#pragma unroll 4
    for (int s = 0; s < 128; s += 8) {
        a0 = fmaf(__ldg(&ab[s + 0]), __ldg(&xb[(size_t)(s + 0) * HH]), a0);
        a1 = fmaf(__ldg(&ab[s + 1]), __ldg(&xb[(size_t)(s + 1) * HH]), a1);
        a2 = fmaf(__ldg(&ab[s + 2]), __ldg(&xb[(size_t)(s + 2) * HH]), a2);
        a3 = fmaf(__ldg(&ab[s + 3]), __ldg(&xb[(size_t)(s + 3) * HH]), a3);
        a4 = fmaf(__ldg(&ab[s + 4]), __ldg(&xb[(size_t)(s + 4) * HH]), a4);
        a5 = fmaf(__ldg(&ab[s + 5]), __ldg(&xb[(size_t)(s + 5) * HH]), a5);
        a6 = fmaf(__ldg(&ab[s + 6]), __ldg(&xb[(size_t)(s + 6) * HH]), a6);
        a7 = fmaf(__ldg(&ab[s + 7]), __ldg(&xb[(size_t)(s + 7) * HH]), a7);
    }
    part[((size_t)sc * BB + b) * HH + h] =
        ((a0 + a1) + (a2 + a3)) + ((a4 + a5) + (a6 + a7));
}

__global__ __launch_bounds__(256)
void weighted_reduce_kernel(const float* __restrict__ part,
                            float* __restrict__ out)
{
    int idx = blockIdx.x * 256 + threadIdx.x;   // BB*HH = 32768
    float s = 0.f;
#pragma unroll
    for (int j = 0; j < 16; j++) s += part[j * BB * HH + idx];
    out[idx] = s;
}

// ---------------------------------------------------------------------------
extern "C" void kernel_launch(void* const* d_in, const int* in_sizes, int n_in,
                              void* d_out, int out_size)
{
    const float* X    = (const float*)d_in[0];   // [B,S,H]
    const void*  mask = d_in[1];                 // [B,S] bool (int32 or uint8)
    const float* W    = (const float*)d_in[2];   // [H,H]
    const float* bias = (const float*)d_in[3];   // [H]
    const float* v    = (const float*)d_in[4];   // [H]
    float* out = (float*)d_out;

    // Output layout: weighted_output [B,H] first, attn_weights [B,S] second.
    float* attn;
    if (out_size >= BB * HH + TOK) {
        attn = out + BB * HH;
    } else {
        void* p = nullptr;
        cudaGetSymbolAddress(&p, g_attn_fallback);
        attn = (float*)p;
    }
    void* sp = nullptr; cudaGetSymbolAddress(&sp, g_scores);
    float* scores = (float*)sp;
    void* pp = nullptr; cudaGetSymbolAddress(&pp, g_part);
    float* part = (float*)pp;
    void* whp = nullptr; cudaGetSymbolAddress(&whp, g_wh);
    void* wlp = nullptr; cudaGetSymbolAddress(&wlp, g_wl);
    __half* wh = (__half*)whp;
    __half* wl = (__half*)wlp;

    cudaFuncSetAttribute(scores_tc_kernel,
                         cudaFuncAttributeMaxDynamicSharedMemorySize, SMEM_TOTAL);

    detect_mask_kernel<<<1, 256>>>((const unsigned*)mask);
    wsplit_kernel<<<HH * HH / 1024, 256>>>(W, wh, wl);
    scores_tc_kernel<<<GRID_M, NTHR, SMEM_TOTAL>>>(X, wh, wl, bias, v, scores);
    softmax_kernel<<<BB, 256>>>(scores, mask, attn);
    weighted_part_kernel<<<dim3(BB, HH / 128, 16), 128>>>(X, attn, part);
    weighted_reduce_kernel<<<BB * HH / 256, 256>>>(part, out);
}

// round 16
// speedup vs baseline: 1.0459x; 1.0048x over previous
#include <cuda_runtime.h>
#include <cuda_fp16.h>
#include <cstdint>
#include <math.h>

// Problem dims (fixed by the reference)
#define BB 64
#define SS 2048
#define HH 512
#define TOK (BB * SS)   // 131072
#define NEGV -1e9f

// Scratch (allocations are banned; use device globals)
__device__ float g_scores[TOK];
__device__ float g_attn_fallback[TOK];
__device__ float g_part[16 * BB * HH];
__device__ int   g_mask_is_i32;
__device__ __half g_wh[HH * HH];
__device__ __half g_wl[HH * HH];

// ===========================================================================
// Helpers
// ===========================================================================
__device__ __forceinline__ uint32_t smem_u32(const void* p) {
    uint32_t a;
    asm("{ .reg .u64 t; cvta.to.shared.u64 t, %1; cvt.u32.u64 %0, t; }"
        : "=r"(a) : "l"(p));
    return a;
}
__device__ __forceinline__ void ldsm4(uint32_t (&r)[4], uint32_t addr) {
    asm volatile("ldmatrix.sync.aligned.m8n8.x4.shared.b16 {%0,%1,%2,%3}, [%4];"
        : "=r"(r[0]), "=r"(r[1]), "=r"(r[2]), "=r"(r[3]) : "r"(addr));
}
// fp16 in, fp32 accum
__device__ __forceinline__ void mma_f32(float (&c)[4], const uint32_t (&a)[4],
                                        uint32_t b0, uint32_t b1) {
    asm volatile("mma.sync.aligned.m16n8k16.row.col.f32.f16.f16.f32 "
        "{%0,%1,%2,%3}, {%4,%5,%6,%7}, {%8,%9}, {%0,%1,%2,%3};"
        : "+f"(c[0]), "+f"(c[1]), "+f"(c[2]), "+f"(c[3])
        : "r"(a[0]), "r"(a[1]), "r"(a[2]), "r"(a[3]), "r"(b0), "r"(b1));
}
// fp16 in, fp16 accum
__device__ __forceinline__ void mma_f16(uint32_t (&c)[2], const uint32_t (&a)[4],
                                        uint32_t b0, uint32_t b1) {
    asm volatile("mma.sync.aligned.m16n8k16.row.col.f16.f16.f16.f16 "
        "{%0,%1}, {%2,%3,%4,%5}, {%6,%7}, {%0,%1};"
        : "+r"(c[0]), "+r"(c[1])
        : "r"(a[0]), "r"(a[1]), "r"(a[2]), "r"(a[3]), "r"(b0), "r"(b1));
}
__device__ __forceinline__ void cp16(uint32_t dst, const void* src) {
    asm volatile("cp.async.cg.shared.global [%0], [%1], 16;"
        :: "r"(dst), "l"(src));
}
#define CP_COMMIT() asm volatile("cp.async.commit_group;" ::: "memory")
#define CP_WAIT0()  asm volatile("cp.async.wait_group 0;" ::: "memory")

__device__ __forceinline__ float fast_tanh(float x) {
    x = fminf(15.f, fmaxf(-15.f, x));
    float e = __expf(2.f * x);
    return __fdividef(e - 1.f, e + 1.f);
}

// ===========================================================================
// W pre-split: W fp32 -> Wh, Wl fp16 (global, done once per launch)
// ===========================================================================
__global__ __launch_bounds__(256)
void wsplit_kernel(const float* __restrict__ W,
                   __half* __restrict__ wh,
                   __half* __restrict__ wl)
{
    int idx = blockIdx.x * 256 + threadIdx.x;
#pragma unroll
    for (int j = 0; j < 4; j++) {
        int i = idx * 4 + j;
        float x = W[i];
        __half h = __float2half_rn(x);
        wh[i] = h;
        wl[i] = __float2half_rn(x - __half2float(h));
    }
}

// ===========================================================================
// Scores kernel (R12 config — best measured): 3-term fp16 split GEMM +
// fused v.tanh(.+b) epilogue. m48n32 warp tiles, block M=96 x N=128, BK=32,
// 256 thr, 2 CTAs/SM, A streamed (LDG fp32 -> hi/lo ring), B via cp.async.
// ===========================================================================
#define ASTR 80                  // 32 fp16 = 64B + 16 pad
#define A_PLANE (96 * ASTR)      // 7680
#define A_STAGE (2 * A_PLANE)    // 15360 (hi+lo)
#define B_PLANE (128 * ASTR)     // 10240
#define B_STAGE (2 * B_PLANE)    // 20480 (hi+lo)
#define OFF_V    0
#define OFF_BI   2048
#define OFF_A    4096
#define OFF_B    (OFF_A + 2 * A_STAGE)      // 34816
#define SMEM_TOTAL (OFF_B + 2 * B_STAGE)    // 75776 -> 2 CTAs/SM
#define OFF_RED  OFF_B                      // reuse dead B ring for reduction

#define NTHR 256
#define BM 96
#define GRID_M ((TOK + BM - 1) / BM)        // 1366

__device__ __forceinline__ void issue_b(const __half* __restrict__ wh,
                                        const __half* __restrict__ wl,
                                        uint32_t dst_hi, int nc, int kt, int tid)
{
#pragma unroll
    for (int j = 0; j < 2; j++) {
        int idx = tid + j * NTHR;         // 0..511
        int row = idx >> 2;               // n row 0..127
        int c16 = idx & 3;                // 16B chunk (4 per 64B row)
        uint32_t d = dst_hi + row * ASTR + c16 * 16;
        size_t g = (size_t)(nc * 128 + row) * HH + kt * 32 + c16 * 8;
        cp16(d, wh + g);
        cp16(d + B_PLANE, wl + g);
    }
    CP_COMMIT();
}

// Convert 3 float4 (96x32 A chunk slice per thread) and store hi/lo.
__device__ __forceinline__ void store_a(const float4 (&ar)[3],
                                        char* ah, char* al, int tid)
{
#pragma unroll
    for (int j = 0; j < 3; j++) {
        int idx = tid + j * NTHR;         // 0..767
        int r  = idx >> 3;                // row 0..95
        int c  = (idx & 7) * 4;           // col (fp32 units, 0..28)
        float4 f = ar[j];
        __half h0 = __float2half_rn(f.x);
        __half h1 = __float2half_rn(f.y);
        __half h2 = __float2half_rn(f.z);
        __half h3 = __float2half_rn(f.w);
        uint32_t hh0 = ((uint32_t)__half_as_ushort(h1) << 16) | __half_as_ushort(h0);
        uint32_t hh1 = ((uint32_t)__half_as_ushort(h3) << 16) | __half_as_ushort(h2);
        __half l0 = __float2half_rn(f.x - __half2float(h0));
        __half l1 = __float2half_rn(f.y - __half2float(h1));
        __half l2 = __float2half_rn(f.z - __half2float(h2));
        __half l3 = __float2half_rn(f.w - __half2float(h3));
        uint32_t ll0 = ((uint32_t)__half_as_ushort(l1) << 16) | __half_as_ushort(l0);
        uint32_t ll1 = ((uint32_t)__half_as_ushort(l3) << 16) | __half_as_ushort(l2);
        int off = r * ASTR + c * 2;
        *(uint2*)(ah + off) = make_uint2(hh0, hh1);
        *(uint2*)(al + off) = make_uint2(ll0, ll1);
    }
}

__device__ __forceinline__ void load_a_chunk(const float* __restrict__ X,
                                             float4 (&ar)[3], int row0, int kt, int tid)
{
#pragma unroll
    for (int j = 0; j < 3; j++) {
        int idx = tid + j * NTHR;
        int r  = idx >> 3;
        int c  = (idx & 7) * 4;
        int rg = row0 + r;
        rg = rg < TOK ? rg : TOK - 1;    // tail clamp
        ar[j] = *(const float4*)(X + (size_t)rg * HH + kt * 32 + c);
    }
}

__global__ __launch_bounds__(NTHR, 2)
void scores_tc_kernel(const float* __restrict__ X,
                      const __half* __restrict__ wh,
                      const __half* __restrict__ wl,
                      const float* __restrict__ bias,
                      const float* __restrict__ v,
                      float* __restrict__ scores)
{
    extern __shared__ char smem[];
    const int tid  = threadIdx.x;
    const int lane = tid & 31;
    const int wid  = tid >> 5;
    const int warp_m = wid & 1;        // 0..1 -> 48-row slab
    const int warp_n = wid >> 1;       // 0..3 -> 32-col slab
    const int row0 = blockIdx.x * BM;

    const uint32_t sb = smem_u32(smem);
    float* sv  = (float*)(smem + OFF_V);
    float* sbi = (float*)(smem + OFF_BI);
    for (int i = tid; i < HH; i += NTHR) { sv[i] = v[i]; sbi[i] = bias[i]; }

    // Prefetch first B tile (it = 0 -> buf 0).
    issue_b(wh, wl, sb + OFF_B, 0, 0, tid);

    // Prologue: A chunk kt=0 -> stage 0.
    {
        float4 ar[3];
        load_a_chunk(X, ar, row0, 0, tid);
        store_a(ar, smem + OFF_A, smem + OFF_A + A_PLANE, tid);
    }

    // ldmatrix lane offsets (bytes)
    const int a_off = (warp_m * 48 + (lane & 15)) * ASTR + ((lane >> 4) << 4);
    const int b_off = (warp_n * 32 + (lane & 7) + ((lane >> 4) << 3)) * ASTR
                    + (((lane >> 3) & 1) << 4);

    float sacc[6] = {0.f, 0.f, 0.f, 0.f, 0.f, 0.f};   // [mi*2 + half]

    for (int nc = 0; nc < 4; nc++) {
        float acc[3][4][4];
        uint32_t corr[3][4][2];
#pragma unroll
        for (int mi = 0; mi < 3; mi++)
#pragma unroll
            for (int ni = 0; ni < 4; ni++) {
#pragma unroll
                for (int c = 0; c < 4; c++) acc[mi][ni][c] = 0.f;
                corr[mi][ni][0] = 0u; corr[mi][ni][1] = 0u;
            }

        for (int kt = 0; kt < 16; kt++) {
            const int it = nc * 16 + kt;
            const int buf = it & 1;
            const bool have_next = (it < 63);

            CP_WAIT0();
            __syncthreads();        // A+B stage(kt) ready; prev stages free

            if (have_next) {
                int nit = it + 1;
                issue_b(wh, wl, sb + OFF_B + (buf ^ 1) * B_STAGE,
                        nit >> 4, nit & 15, tid);
            }

            // Prefetch next A chunk (fp32) into regs; latency hidden by MMAs.
            float4 ar[3];
            if (have_next) load_a_chunk(X, ar, row0, (kt + 1) & 15, tid);

            const uint32_t ah_base = sb + OFF_A + buf * A_STAGE + a_off;
            const uint32_t al_base = ah_base + A_PLANE;
            const uint32_t bh_b = sb + OFF_B + buf * B_STAGE + b_off;
            const uint32_t bl_b = bh_b + B_PLANE;

#pragma unroll
            for (int k16 = 0; k16 < 2; k16++) {
                const int ko = k16 * 32;
                uint32_t ah0[4], ah1[4], ah2[4], al0[4], al1[4], al2[4];
                ldsm4(ah0, ah_base + ko);
                ldsm4(ah1, ah_base + 1280 + ko);    // +16 rows
                ldsm4(ah2, ah_base + 2560 + ko);    // +32 rows
                ldsm4(al0, al_base + ko);
                ldsm4(al1, al_base + 1280 + ko);
                ldsm4(al2, al_base + 2560 + ko);
#pragma unroll
                for (int np = 0; np < 2; np++) {
                    const int bo = np * 1280 + ko;
                    uint32_t bh[4], bl[4];
                    ldsm4(bh, bh_b + bo);
                    ldsm4(bl, bl_b + bo);
                    // main terms: fp32 accumulate
                    mma_f32(acc[0][2 * np],     ah0, bh[0], bh[1]);
                    mma_f32(acc[0][2 * np + 1], ah0, bh[2], bh[3]);
                    mma_f32(acc[1][2 * np],     ah1, bh[0], bh[1]);
                    mma_f32(acc[1][2 * np + 1], ah1, bh[2], bh[3]);
                    mma_f32(acc[2][2 * np],     ah2, bh[0], bh[1]);
                    mma_f32(acc[2][2 * np + 1], ah2, bh[2], bh[3]);
                    // corrections: fp16 accumulate; RAW pairs spaced.
                    mma_f16(corr[0][2 * np],     ah0, bl[0], bl[1]);
                    mma_f16(corr[0][2 * np + 1], ah0, bl[2], bl[3]);
                    mma_f16(corr[1][2 * np],     ah1, bl[0], bl[1]);
                    mma_f16(corr[1][2 * np + 1], ah1, bl[2], bl[3]);
                    mma_f16(corr[2][2 * np],     ah2, bl[0], bl[1]);
                    mma_f16(corr[2][2 * np + 1], ah2, bl[2], bl[3]);
                    mma_f16(corr[0][2 * np],     al0, bh[0], bh[1]);
                    mma_f16(corr[0][2 * np + 1], al0, bh[2], bh[3]);
                    mma_f16(corr[1][2 * np],     al1, bh[0], bh[1]);
                    mma_f16(corr[1][2 * np + 1], al1, bh[2], bh[3]);
                    mma_f16(corr[2][2 * np],     al2, bh[0], bh[1]);
                    mma_f16(corr[2][2 * np + 1], al2, bh[2], bh[3]);
                }
            }

            // Convert + store next A chunk into the other stage.
            if (have_next) {
                char* ahd = smem + OFF_A + (buf ^ 1) * A_STAGE;
                store_a(ar, ahd, ahd + A_PLANE, tid);
            }
        }

        // fused partial epilogue for this 128-col chunk
#pragma unroll
        for (int mi = 0; mi < 3; mi++)
#pragma unroll
            for (int ni = 0; ni < 4; ni++) {
                float2 c01 = __half22float2(*(const __half2*)&corr[mi][ni][0]);
                float2 c23 = __half22float2(*(const __half2*)&corr[mi][ni][1]);
                float cf[4] = {c01.x, c01.y, c23.x, c23.y};
#pragma unroll
                for (int c = 0; c < 4; c++) {
                    int n = nc * 128 + warp_n * 32 + ni * 8 + (lane & 3) * 2 + (c & 1);
                    float t = fast_tanh(acc[mi][ni][c] + cf[c] + sbi[n]);
                    sacc[mi * 2 + (c >> 1)] = fmaf(sv[n], t, sacc[mi * 2 + (c >> 1)]);
                }
            }
    }

    // cross-warp reduction: red[96][16] aliases the (dead) B ring.
    float* red = (float*)(smem + OFF_RED);
    __syncthreads();   // all B/A reads done before aliasing
#pragma unroll
    for (int mi = 0; mi < 3; mi++)
#pragma unroll
        for (int half = 0; half < 2; half++) {
            int m = warp_m * 48 + mi * 16 + half * 8 + (lane >> 2);
            red[m * 16 + warp_n * 4 + (lane & 3)] = sacc[mi * 2 + half];
        }
    __syncthreads();
    if (tid < BM) {
        float s = 0.f;
#pragma unroll
        for (int j = 0; j < 16; j++) s += red[tid * 16 + j];
        if (row0 + tid < TOK) scores[row0 + tid] = s;
    }
}

// ---------------------------------------------------------------------------
// Mask dtype detection (parallel): 256 threads each test one uint32 word;
// if all words <= 1 the mask is int32-serialized bool, else uint8.
// ---------------------------------------------------------------------------
__global__ __launch_bounds__(256)
void detect_mask_kernel(const unsigned* __restrict__ mask_words)
{
    __shared__ int bad;
    if (threadIdx.x == 0) bad = 0;
    __syncthreads();
    if (mask_words[threadIdx.x] > 1u) bad = 1;
    __syncthreads();
    if (threadIdx.x == 0) g_mask_is_i32 = bad ? 0 : 1;
}

// ---------------------------------------------------------------------------
// Masked softmax over S per batch row (512 threads, 4 chunks/thread).
// ---------------------------------------------------------------------------
__global__ __launch_bounds__(512)
void softmax_kernel(const float* __restrict__ scores,
                    const void* __restrict__ mask,
                    float* __restrict__ attn)
{
    const int b = blockIdx.x;
    const int tid = threadIdx.x;
    __shared__ float sred[512];
    __shared__ int s_is_i32;

    if (tid == 0) s_is_i32 = g_mask_is_i32;
    __syncthreads();
    const int is_i32 = s_is_i32;

    const int* mi = (const int*)mask;
    const unsigned char* mu = (const unsigned char*)mask;

    float vals[4];
    float mx = -INFINITY;
#pragma unroll
    for (int j = 0; j < 4; j++) {
        int idx = b * SS + tid + j * 512;
        float sc = scores[idx];
        bool m = is_i32 ? (mi[idx] != 0) : (mu[idx] != 0);
        sc = m ? sc : NEGV;
        vals[j] = sc;
        mx = fmaxf(mx, sc);
    }
    sred[tid] = mx; __syncthreads();
    for (int off = 256; off > 0; off >>= 1) {
        if (tid < off) sred[tid] = fmaxf(sred[tid], sred[tid + off]);
        __syncthreads();
    }
    mx = sred[0]; __syncthreads();

    float sum = 0.f;
#pragma unroll
    for (int j = 0; j < 4; j++) {
        vals[j] = expf(vals[j] - mx);
        sum += vals[j];
    }
    sred[tid] = sum; __syncthreads();
    for (int off = 256; off > 0; off >>= 1) {
        if (tid < off) sred[tid] += sred[tid + off];
        __syncthreads();
    }
    sum = sred[0];

    float inv = 1.f / sum;
#pragma unroll
    for (int j = 0; j < 4; j++) {
        attn[b * SS + tid + j * 512] = vals[j] * inv;
    }
}

// ---------------------------------------------------------------------------
// weighted_output[b,h] = sum_s attn[b,s] * X[b,s,h]
// Stage 1: S split 16 ways, attn chunk staged in SMEM (halves LDG issue),
// 8 independent FMA chains (grid 64x4x16). Stage 2: reduce 16 partials.
// ---------------------------------------------------------------------------
__global__ __launch_bounds__(128)
void weighted_part_kernel(const float* __restrict__ X,
                          const float* __restrict__ attn,
                          float* __restrict__ part)
{
    __shared__ float sa[128];
    const int b  = blockIdx.x;
    const int h  = blockIdx.y * 128 + threadIdx.x;
    const int sc = blockIdx.z;              // 0..15, 128 s each
    const int s0 = sc * 128;
    const float* xb = X + (size_t)b * SS * HH + (size_t)s0 * HH + h;

    sa[threadIdx.x] = attn[b * SS + s0 + threadIdx.x];
    __syncthreads();

    float a0 = 0.f, a1 = 0.f, a2 = 0.f, a3 = 0.f;
    float a4 = 0.f, a5 = 0.f, a6 = 0.f, a7 = 0.f;
#pragma unroll 4
    for (int s = 0; s < 128; s += 8) {
        a0 = fmaf(sa[s + 0], __ldg(&xb[(size_t)(s + 0) * HH]), a0);
        a1 = fmaf(sa[s + 1], __ldg(&xb[(size_t)(s + 1) * HH]), a1);
        a2 = fmaf(sa[s + 2], __ldg(&xb[(size_t)(s + 2) * HH]), a2);
        a3 = fmaf(sa[s + 3], __ldg(&xb[(size_t)(s + 3) * HH]), a3);
        a4 = fmaf(sa[s + 4], __ldg(&xb[(size_t)(s + 4) * HH]), a4);
        a5 = fmaf(sa[s + 5], __ldg(&xb[(size_t)(s + 5) * HH]), a5);
        a6 = fmaf(sa[s + 6], __ldg(&xb[(size_t)(s + 6) * HH]), a6);
        a7 = fmaf(sa[s + 7], __ldg(&xb[(size_t)(s + 7) * HH]), a7);
    }
    part[((size_t)sc * BB + b) * HH + h] =
        ((a0 + a1) + (a2 + a3)) + ((a4 + a5) + (a6 + a7));
}

__global__ __launch_bounds__(256)
void weighted_reduce_kernel(const float* __restrict__ part,
                            float* __restrict__ out)
{
    int idx = blockIdx.x * 256 + threadIdx.x;   // BB*HH = 32768
    float s = 0.f;
#pragma unroll
    for (int j = 0; j < 16; j++) s += part[j * BB * HH + idx];
    out[idx] = s;
}

// ---------------------------------------------------------------------------
extern "C" void kernel_launch(void* const* d_in, const int* in_sizes, int n_in,
                              void* d_out, int out_size)
{
    const float* X    = (const float*)d_in[0];   // [B,S,H]
    const void*  mask = d_in[1];                 // [B,S] bool (int32 or uint8)
    const float* W    = (const float*)d_in[2];   // [H,H]
    const float* bias = (const float*)d_in[3];   // [H]
    const float* v    = (const float*)d_in[4];   // [H]
    float* out = (float*)d_out;

    // Output layout: weighted_output [B,H] first, attn_weights [B,S] second.
    float* attn;
    if (out_size >= BB * HH + TOK) {
        attn = out + BB * HH;
    } else {
        void* p = nullptr;
        cudaGetSymbolAddress(&p, g_attn_fallback);
        attn = (float*)p;
    }
    void* sp = nullptr; cudaGetSymbolAddress(&sp, g_scores);
    float* scores = (float*)sp;
    void* pp = nullptr; cudaGetSymbolAddress(&pp, g_part);
    float* part = (float*)pp;
    void* whp = nullptr; cudaGetSymbolAddress(&whp, g_wh);
    void* wlp = nullptr; cudaGetSymbolAddress(&wlp, g_wl);
    __half* wh = (__half*)whp;
    __half* wl = (__half*)wlp;

    cudaFuncSetAttribute(scores_tc_kernel,
                         cudaFuncAttributeMaxDynamicSharedMemorySize, SMEM_TOTAL);

    detect_mask_kernel<<<1, 256>>>((const unsigned*)mask);
    wsplit_kernel<<<HH * HH / 1024, 256>>>(W, wh, wl);
    scores_tc_kernel<<<GRID_M, NTHR, SMEM_TOTAL>>>(X, wh, wl, bias, v, scores);
    softmax_kernel<<<BB, 512>>>(scores, mask, attn);
    weighted_part_kernel<<<dim3(BB, HH / 128, 16), 128>>>(X, attn, part);
    weighted_reduce_kernel<<<BB * HH / 256, 256>>>(part, out);
}

// round 17
// speedup vs baseline: 1.0482x; 1.0022x over previous
#include <cuda_runtime.h>
#include <cuda_fp16.h>
#include <cstdint>
#include <math.h>

// Problem dims (fixed by the reference)
#define BB 64
#define SS 2048
#define HH 512
#define TOK (BB * SS)   // 131072
#define NEGV -1e9f

// Scratch (allocations are banned; use device globals)
__device__ float g_scores[TOK];
__device__ float g_attn_fallback[TOK];
__device__ float g_part[16 * BB * HH];
__device__ int   g_mask_is_i32;
__device__ __half g_wh[HH * HH];
__device__ __half g_wl[HH * HH];

// ===========================================================================
// Helpers
// ===========================================================================
__device__ __forceinline__ uint32_t smem_u32(const void* p) {
    uint32_t a;
    asm("{ .reg .u64 t; cvta.to.shared.u64 t, %1; cvt.u32.u64 %0, t; }"
        : "=r"(a) : "l"(p));
    return a;
}
__device__ __forceinline__ void ldsm4(uint32_t (&r)[4], uint32_t addr) {
    asm volatile("ldmatrix.sync.aligned.m8n8.x4.shared.b16 {%0,%1,%2,%3}, [%4];"
        : "=r"(r[0]), "=r"(r[1]), "=r"(r[2]), "=r"(r[3]) : "r"(addr));
}
// fp16 in, fp32 accum
__device__ __forceinline__ void mma_f32(float (&c)[4], const uint32_t (&a)[4],
                                        uint32_t b0, uint32_t b1) {
    asm volatile("mma.sync.aligned.m16n8k16.row.col.f32.f16.f16.f32 "
        "{%0,%1,%2,%3}, {%4,%5,%6,%7}, {%8,%9}, {%0,%1,%2,%3};"
        : "+f"(c[0]), "+f"(c[1]), "+f"(c[2]), "+f"(c[3])
        : "r"(a[0]), "r"(a[1]), "r"(a[2]), "r"(a[3]), "r"(b0), "r"(b1));
}
// fp16 in, fp16 accum
__device__ __forceinline__ void mma_f16(uint32_t (&c)[2], const uint32_t (&a)[4],
                                        uint32_t b0, uint32_t b1) {
    asm volatile("mma.sync.aligned.m16n8k16.row.col.f16.f16.f16.f16 "
        "{%0,%1}, {%2,%3,%4,%5}, {%6,%7}, {%0,%1};"
        : "+r"(c[0]), "+r"(c[1])
        : "r"(a[0]), "r"(a[1]), "r"(a[2]), "r"(a[3]), "r"(b0), "r"(b1));
}
__device__ __forceinline__ void cp16(uint32_t dst, const void* src) {
    asm volatile("cp.async.cg.shared.global [%0], [%1], 16;"
        :: "r"(dst), "l"(src));
}
#define CP_COMMIT() asm volatile("cp.async.commit_group;" ::: "memory")
#define CP_WAIT0()  asm volatile("cp.async.wait_group 0;" ::: "memory")

__device__ __forceinline__ float fast_tanh(float x) {
    x = fminf(15.f, fmaxf(-15.f, x));
    float e = __expf(2.f * x);
    return __fdividef(e - 1.f, e + 1.f);
}

// ===========================================================================
// W pre-split (W fp32 -> Wh, Wl fp16) + fused mask dtype detection.
// Block 0 additionally scans the first 256 mask words: if all <= 1, the mask
// was serialized as int32; otherwise uint8. Result used by softmax (3 launches
// later), so no ordering hazard.
// ===========================================================================
__global__ __launch_bounds__(256)
void wsplit_detect_kernel(const float* __restrict__ W,
                          __half* __restrict__ wh,
                          __half* __restrict__ wl,
                          const unsigned* __restrict__ mask_words)
{
    int idx = blockIdx.x * 256 + threadIdx.x;
#pragma unroll
    for (int j = 0; j < 4; j++) {
        int i = idx * 4 + j;
        float x = W[i];
        __half h = __float2half_rn(x);
        wh[i] = h;
        wl[i] = __float2half_rn(x - __half2float(h));
    }
    if (blockIdx.x == 0) {
        __shared__ int bad;
        if (threadIdx.x == 0) bad = 0;
        __syncthreads();
        if (mask_words[threadIdx.x] > 1u) bad = 1;
        __syncthreads();
        if (threadIdx.x == 0) g_mask_is_i32 = bad ? 0 : 1;
    }
}

// ===========================================================================
// Scores kernel (R12 config — best measured): 3-term fp16 split GEMM +
// fused v.tanh(.+b) epilogue. m48n32 warp tiles, block M=96 x N=128, BK=32,
// 256 thr, 2 CTAs/SM, A streamed (LDG fp32 -> hi/lo ring), B via cp.async.
// ===========================================================================
#define ASTR 80                  // 32 fp16 = 64B + 16 pad
#define A_PLANE (96 * ASTR)      // 7680
#define A_STAGE (2 * A_PLANE)    // 15360 (hi+lo)
#define B_PLANE (128 * ASTR)     // 10240
#define B_STAGE (2 * B_PLANE)    // 20480 (hi+lo)
#define OFF_V    0
#define OFF_BI   2048
#define OFF_A    4096
#define OFF_B    (OFF_A + 2 * A_STAGE)      // 34816
#define SMEM_TOTAL (OFF_B + 2 * B_STAGE)    // 75776 -> 2 CTAs/SM
#define OFF_RED  OFF_B                      // reuse dead B ring for reduction

#define NTHR 256
#define BM 96
#define GRID_M ((TOK + BM - 1) / BM)        // 1366

__device__ __forceinline__ void issue_b(const __half* __restrict__ wh,
                                        const __half* __restrict__ wl,
                                        uint32_t dst_hi, int nc, int kt, int tid)
{
#pragma unroll
    for (int j = 0; j < 2; j++) {
        int idx = tid + j * NTHR;         // 0..511
        int row = idx >> 2;               // n row 0..127
        int c16 = idx & 3;                // 16B chunk (4 per 64B row)
        uint32_t d = dst_hi + row * ASTR + c16 * 16;
        size_t g = (size_t)(nc * 128 + row) * HH + kt * 32 + c16 * 8;
        cp16(d, wh + g);
        cp16(d + B_PLANE, wl + g);
    }
    CP_COMMIT();
}

// Convert 3 float4 (96x32 A chunk slice per thread) and store hi/lo.
__device__ __forceinline__ void store_a(const float4 (&ar)[3],
                                        char* ah, char* al, int tid)
{
#pragma unroll
    for (int j = 0; j < 3; j++) {
        int idx = tid + j * NTHR;         // 0..767
        int r  = idx >> 3;                // row 0..95
        int c  = (idx & 7) * 4;           // col (fp32 units, 0..28)
        float4 f = ar[j];
        __half h0 = __float2half_rn(f.x);
        __half h1 = __float2half_rn(f.y);
        __half h2 = __float2half_rn(f.z);
        __half h3 = __float2half_rn(f.w);
        uint32_t hh0 = ((uint32_t)__half_as_ushort(h1) << 16) | __half_as_ushort(h0);
        uint32_t hh1 = ((uint32_t)__half_as_ushort(h3) << 16) | __half_as_ushort(h2);
        __half l0 = __float2half_rn(f.x - __half2float(h0));
        __half l1 = __float2half_rn(f.y - __half2float(h1));
        __half l2 = __float2half_rn(f.z - __half2float(h2));
        __half l3 = __float2half_rn(f.w - __half2float(h3));
        uint32_t ll0 = ((uint32_t)__half_as_ushort(l1) << 16) | __half_as_ushort(l0);
        uint32_t ll1 = ((uint32_t)__half_as_ushort(l3) << 16) | __half_as_ushort(l2);
        int off = r * ASTR + c * 2;
        *(uint2*)(ah + off) = make_uint2(hh0, hh1);
        *(uint2*)(al + off) = make_uint2(ll0, ll1);
    }
}

__device__ __forceinline__ void load_a_chunk(const float* __restrict__ X,
                                             float4 (&ar)[3], int row0, int kt, int tid)
{
#pragma unroll
    for (int j = 0; j < 3; j++) {
        int idx = tid + j * NTHR;
        int r  = idx >> 3;
        int c  = (idx & 7) * 4;
        int rg = row0 + r;
        rg = rg < TOK ? rg : TOK - 1;    // tail clamp
        ar[j] = *(const float4*)(X + (size_t)rg * HH + kt * 32 + c);
    }
}

__global__ __launch_bounds__(NTHR, 2)
void scores_tc_kernel(const float* __restrict__ X,
                      const __half* __restrict__ wh,
                      const __half* __restrict__ wl,
                      const float* __restrict__ bias,
                      const float* __restrict__ v,
                      float* __restrict__ scores)
{
    extern __shared__ char smem[];
    const int tid  = threadIdx.x;
    const int lane = tid & 31;
    const int wid  = tid >> 5;
    const int warp_m = wid & 1;        // 0..1 -> 48-row slab
    const int warp_n = wid >> 1;       // 0..3 -> 32-col slab
    const int row0 = blockIdx.x * BM;

    const uint32_t sb = smem_u32(smem);
    float* sv  = (float*)(smem + OFF_V);
    float* sbi = (float*)(smem + OFF_BI);
    for (int i = tid; i < HH; i += NTHR) { sv[i] = v[i]; sbi[i] = bias[i]; }

    // Prefetch first B tile (it = 0 -> buf 0).
    issue_b(wh, wl, sb + OFF_B, 0, 0, tid);

    // Prologue: A chunk kt=0 -> stage 0.
    {
        float4 ar[3];
        load_a_chunk(X, ar, row0, 0, tid);
        store_a(ar, smem + OFF_A, smem + OFF_A + A_PLANE, tid);
    }

    // ldmatrix lane offsets (bytes)
    const int a_off = (warp_m * 48 + (lane & 15)) * ASTR + ((lane >> 4) << 4);
    const int b_off = (warp_n * 32 + (lane & 7) + ((lane >> 4) << 3)) * ASTR
                    + (((lane >> 3) & 1) << 4);

    float sacc[6] = {0.f, 0.f, 0.f, 0.f, 0.f, 0.f};   // [mi*2 + half]

    for (int nc = 0; nc < 4; nc++) {
        float acc[3][4][4];
        uint32_t corr[3][4][2];
#pragma unroll
        for (int mi = 0; mi < 3; mi++)
#pragma unroll
            for (int ni = 0; ni < 4; ni++) {
#pragma unroll
                for (int c = 0; c < 4; c++) acc[mi][ni][c] = 0.f;
                corr[mi][ni][0] = 0u; corr[mi][ni][1] = 0u;
            }

        for (int kt = 0; kt < 16; kt++) {
            const int it = nc * 16 + kt;
            const int buf = it & 1;
            const bool have_next = (it < 63);

            CP_WAIT0();
            __syncthreads();        // A+B stage(kt) ready; prev stages free

            if (have_next) {
                int nit = it + 1;
                issue_b(wh, wl, sb + OFF_B + (buf ^ 1) * B_STAGE,
                        nit >> 4, nit & 15, tid);
            }

            // Prefetch next A chunk (fp32) into regs; latency hidden by MMAs.
            float4 ar[3];
            if (have_next) load_a_chunk(X, ar, row0, (kt + 1) & 15, tid);

            const uint32_t ah_base = sb + OFF_A + buf * A_STAGE + a_off;
            const uint32_t al_base = ah_base + A_PLANE;
            const uint32_t bh_b = sb + OFF_B + buf * B_STAGE + b_off;
            const uint32_t bl_b = bh_b + B_PLANE;

#pragma unroll
            for (int k16 = 0; k16 < 2; k16++) {
                const int ko = k16 * 32;
                uint32_t ah0[4], ah1[4], ah2[4], al0[4], al1[4], al2[4];
                ldsm4(ah0, ah_base + ko);
                ldsm4(ah1, ah_base + 1280 + ko);    // +16 rows
                ldsm4(ah2, ah_base + 2560 + ko);    // +32 rows
                ldsm4(al0, al_base + ko);
                ldsm4(al1, al_base + 1280 + ko);
                ldsm4(al2, al_base + 2560 + ko);
#pragma unroll
                for (int np = 0; np < 2; np++) {
                    const int bo = np * 1280 + ko;
                    uint32_t bh[4], bl[4];
                    ldsm4(bh, bh_b + bo);
                    ldsm4(bl, bl_b + bo);
                    // main terms: fp32 accumulate
                    mma_f32(acc[0][2 * np],     ah0, bh[0], bh[1]);
                    mma_f32(acc[0][2 * np + 1], ah0, bh[2], bh[3]);
                    mma_f32(acc[1][2 * np],     ah1, bh[0], bh[1]);
                    mma_f32(acc[1][2 * np + 1], ah1, bh[2], bh[3]);
                    mma_f32(acc[2][2 * np],     ah2, bh[0], bh[1]);
                    mma_f32(acc[2][2 * np + 1], ah2, bh[2], bh[3]);
                    // corrections: fp16 accumulate; RAW pairs spaced.
                    mma_f16(corr[0][2 * np],     ah0, bl[0], bl[1]);
                    mma_f16(corr[0][2 * np + 1], ah0, bl[2], bl[3]);
                    mma_f16(corr[1][2 * np],     ah1, bl[0], bl[1]);
                    mma_f16(corr[1][2 * np + 1], ah1, bl[2], bl[3]);
                    mma_f16(corr[2][2 * np],     ah2, bl[0], bl[1]);
                    mma_f16(corr[2][2 * np + 1], ah2, bl[2], bl[3]);
                    mma_f16(corr[0][2 * np],     al0, bh[0], bh[1]);
                    mma_f16(corr[0][2 * np + 1], al0, bh[2], bh[3]);
                    mma_f16(corr[1][2 * np],     al1, bh[0], bh[1]);
                    mma_f16(corr[1][2 * np + 1], al1, bh[2], bh[3]);
                    mma_f16(corr[2][2 * np],     al2, bh[0], bh[1]);
                    mma_f16(corr[2][2 * np + 1], al2, bh[2], bh[3]);
                }
            }

            // Convert + store next A chunk into the other stage.
            if (have_next) {
                char* ahd = smem + OFF_A + (buf ^ 1) * A_STAGE;
                store_a(ar, ahd, ahd + A_PLANE, tid);
            }
        }

        // fused partial epilogue for this 128-col chunk
#pragma unroll
        for (int mi = 0; mi < 3; mi++)
#pragma unroll
            for (int ni = 0; ni < 4; ni++) {
                float2 c01 = __half22float2(*(const __half2*)&corr[mi][ni][0]);
                float2 c23 = __half22float2(*(const __half2*)&corr[mi][ni][1]);
                float cf[4] = {c01.x, c01.y, c23.x, c23.y};
#pragma unroll
                for (int c = 0; c < 4; c++) {
                    int n = nc * 128 + warp_n * 32 + ni * 8 + (lane & 3) * 2 + (c & 1);
                    float t = fast_tanh(acc[mi][ni][c] + cf[c] + sbi[n]);
                    sacc[mi * 2 + (c >> 1)] = fmaf(sv[n], t, sacc[mi * 2 + (c >> 1)]);
                }
            }
    }

    // cross-warp reduction: red[96][16] aliases the (dead) B ring.
    float* red = (float*)(smem + OFF_RED);
    __syncthreads();   // all B/A reads done before aliasing
#pragma unroll
    for (int mi = 0; mi < 3; mi++)
#pragma unroll
        for (int half = 0; half < 2; half++) {
            int m = warp_m * 48 + mi * 16 + half * 8 + (lane >> 2);
            red[m * 16 + warp_n * 4 + (lane & 3)] = sacc[mi * 2 + half];
        }
    __syncthreads();
    if (tid < BM) {
        float s = 0.f;
#pragma unroll
        for (int j = 0; j < 16; j++) s += red[tid * 16 + j];
        if (row0 + tid < TOK) scores[row0 + tid] = s;
    }
}

// ---------------------------------------------------------------------------
// Masked softmax over S per batch row (512 threads, 4 chunks/thread).
// ---------------------------------------------------------------------------
__global__ __launch_bounds__(512)
void softmax_kernel(const float* __restrict__ scores,
                    const void* __restrict__ mask,
                    float* __restrict__ attn)
{
    const int b = blockIdx.x;
    const int tid = threadIdx.x;
    __shared__ float sred[512];
    __shared__ int s_is_i32;

    if (tid == 0) s_is_i32 = g_mask_is_i32;
    __syncthreads();
    const int is_i32 = s_is_i32;

    const int* mi = (const int*)mask;
    const unsigned char* mu = (const unsigned char*)mask;

    float vals[4];
    float mx = -INFINITY;
#pragma unroll
    for (int j = 0; j < 4; j++) {
        int idx = b * SS + tid + j * 512;
        float sc = scores[idx];
        bool m = is_i32 ? (mi[idx] != 0) : (mu[idx] != 0);
        sc = m ? sc : NEGV;
        vals[j] = sc;
        mx = fmaxf(mx, sc);
    }
    sred[tid] = mx; __syncthreads();
    for (int off = 256; off > 0; off >>= 1) {
        if (tid < off) sred[tid] = fmaxf(sred[tid], sred[tid + off]);
        __syncthreads();
    }
    mx = sred[0]; __syncthreads();

    float sum = 0.f;
#pragma unroll
    for (int j = 0; j < 4; j++) {
        vals[j] = expf(vals[j] - mx);
        sum += vals[j];
    }
    sred[tid] = sum; __syncthreads();
    for (int off = 256; off > 0; off >>= 1) {
        if (tid < off) sred[tid] += sred[tid + off];
        __syncthreads();
    }
    sum = sred[0];

    float inv = 1.f / sum;
#pragma unroll
    for (int j = 0; j < 4; j++) {
        attn[b * SS + tid + j * 512] = vals[j] * inv;
    }
}

// ---------------------------------------------------------------------------
// weighted_output[b,h] = sum_s attn[b,s] * X[b,s,h]
// Stage 1: S split 16 ways, attn chunk staged in SMEM (halves LDG issue),
// 8 independent FMA chains (grid 64x4x16). Stage 2: reduce 16 partials.
// ---------------------------------------------------------------------------
__global__ __launch_bounds__(128)
void weighted_part_kernel(const float* __restrict__ X,
                          const float* __restrict__ attn,
                          float* __restrict__ part)
{
    __shared__ float sa[128];
    const int b  = blockIdx.x;
    const int h  = blockIdx.y * 128 + threadIdx.x;
    const int sc = blockIdx.z;              // 0..15, 128 s each
    const int s0 = sc * 128;
    const float* xb = X + (size_t)b * SS * HH + (size_t)s0 * HH + h;

    sa[threadIdx.x] = attn[b * SS + s0 + threadIdx.x];
    __syncthreads();

    float a0 = 0.f, a1 = 0.f, a2 = 0.f, a3 = 0.f;
    float a4 = 0.f, a5 = 0.f, a6 = 0.f, a7 = 0.f;
#pragma unroll 4
    for (int s = 0; s < 128; s += 8) {
        a0 = fmaf(sa[s + 0], __ldg(&xb[(size_t)(s + 0) * HH]), a0);
        a1 = fmaf(sa[s + 1], __ldg(&xb[(size_t)(s + 1) * HH]), a1);
        a2 = fmaf(sa[s + 2], __ldg(&xb[(size_t)(s + 2) * HH]), a2);
        a3 = fmaf(sa[s + 3], __ldg(&xb[(size_t)(s + 3) * HH]), a3);
        a4 = fmaf(sa[s + 4], __ldg(&xb[(size_t)(s + 4) * HH]), a4);
        a5 = fmaf(sa[s + 5], __ldg(&xb[(size_t)(s + 5) * HH]), a5);
        a6 = fmaf(sa[s + 6], __ldg(&xb[(size_t)(s + 6) * HH]), a6);
        a7 = fmaf(sa[s + 7], __ldg(&xb[(size_t)(s + 7) * HH]), a7);
    }
    part[((size_t)sc * BB + b) * HH + h] =
        ((a0 + a1) + (a2 + a3)) + ((a4 + a5) + (a6 + a7));
}

__global__ __launch_bounds__(256)
void weighted_reduce_kernel(const float* __restrict__ part,
                            float* __restrict__ out)
{
    int idx = blockIdx.x * 256 + threadIdx.x;   // BB*HH = 32768
    float s = 0.f;
#pragma unroll
    for (int j = 0; j < 16; j++) s += part[j * BB * HH + idx];
    out[idx] = s;
}

// ---------------------------------------------------------------------------
extern "C" void kernel_launch(void* const* d_in, const int* in_sizes, int n_in,
                              void* d_out, int out_size)
{
    const float* X    = (const float*)d_in[0];   // [B,S,H]
    const void*  mask = d_in[1];                 // [B,S] bool (int32 or uint8)
    const float* W    = (const float*)d_in[2];   // [H,H]
    const float* bias = (const float*)d_in[3];   // [H]
    const float* v    = (const float*)d_in[4];   // [H]
    float* out = (float*)d_out;

    // Output layout: weighted_output [B,H] first, attn_weights [B,S] second.
    float* attn;
    if (out_size >= BB * HH + TOK) {
        attn = out + BB * HH;
    } else {
        void* p = nullptr;
        cudaGetSymbolAddress(&p, g_attn_fallback);
        attn = (float*)p;
    }
    void* sp = nullptr; cudaGetSymbolAddress(&sp, g_scores);
    float* scores = (float*)sp;
    void* pp = nullptr; cudaGetSymbolAddress(&pp, g_part);
    float* part = (float*)pp;
    void* whp = nullptr; cudaGetSymbolAddress(&whp, g_wh);
    void* wlp = nullptr; cudaGetSymbolAddress(&wlp, g_wl);
    __half* wh = (__half*)whp;
    __half* wl = (__half*)wlp;

    cudaFuncSetAttribute(scores_tc_kernel,
                         cudaFuncAttributeMaxDynamicSharedMemorySize, SMEM_TOTAL);

    wsplit_detect_kernel<<<HH * HH / 1024, 256>>>(W, wh, wl, (const unsigned*)mask);
    scores_tc_kernel<<<GRID_M, NTHR, SMEM_TOTAL>>>(X, wh, wl, bias, v, scores);
    softmax_kernel<<<BB, 512>>>(scores, mask, attn);
    weighted_part_kernel<<<dim3(BB, HH / 128, 16), 128>>>(X, attn, part);
    weighted_reduce_kernel<<<BB * HH / 256, 256>>>(part, out);
}